// round 1
// baseline (speedup 1.0000x reference)
#include <cuda_runtime.h>
#include <math.h>

#define CCH   128
#define HIMG  56
#define WIMG  56
#define NIMG  32
#define EPSBN 1e-5f
#define QLEV  255.0f
#define WMAXQ 127.0f

// ---------------- device scratch (no runtime alloc allowed) ----------------
__device__ float g_w1t[CCH * 9 * CCH];                 // [(ci*9+rs)*CCH + co], fake-quantized
__device__ float g_w2t[CCH * 9 * CCH];
__device__ float g_act1[(size_t)NIMG * CCH * HIMG * WIMG]; // 51.4 MB intermediate
__device__ float g_bns1[CCH], g_bnb1[CCH], g_a1[CCH], g_s1[CCH];
__device__ float g_bns2[CCH], g_bnb2[CCH], g_a2[CCH], g_s2[CCH];
__device__ float g_a3[CCH],  g_s3[CCH];

// ---------------- weight fake-quant + transpose ----------------
// grid: (128 out-channels, 2 weight tensors), 256 threads
__global__ void prep_weights(const float* __restrict__ w1,
                             const float* __restrict__ w2) {
    const int o = blockIdx.x;
    const float* w  = (blockIdx.y == 0) ? w1 : w2;
    float* dst      = (blockIdx.y == 0) ? g_w1t : g_w2t;
    const float* wo = w + (size_t)o * CCH * 9;

    float m = 0.f;
    for (int i = threadIdx.x; i < CCH * 9; i += blockDim.x)
        m = fmaxf(m, fabsf(wo[i]));

    __shared__ float red[256];
    red[threadIdx.x] = m;
    __syncthreads();
    for (int s = 128; s > 0; s >>= 1) {
        if (threadIdx.x < s)
            red[threadIdx.x] = fmaxf(red[threadIdx.x], red[threadIdx.x + s]);
        __syncthreads();
    }
    const float scale = fmaxf(red[0] / WMAXQ, 1e-8f);

    for (int i = threadIdx.x; i < CCH * 9; i += blockDim.x) {
        float q = fminf(fmaxf(rintf(wo[i] / scale), -WMAXQ), WMAXQ) * scale;
        dst[(size_t)i * CCH + o] = q;   // i = ci*9 + rs  ->  [ci*9+rs][o]
    }
}

// ---------------- per-channel constant folding ----------------
__global__ void prep_params(const float* __restrict__ g1, const float* __restrict__ b1,
                            const float* __restrict__ m1, const float* __restrict__ v1,
                            const float* __restrict__ a1,
                            const float* __restrict__ g2, const float* __restrict__ b2,
                            const float* __restrict__ m2, const float* __restrict__ v2,
                            const float* __restrict__ a2,
                            const float* __restrict__ a3) {
    const int c = threadIdx.x;
    if (c >= CCH) return;
    float sc1 = g1[c] / sqrtf(v1[c] + EPSBN);
    g_bns1[c] = sc1;
    g_bnb1[c] = b1[c] - m1[c] * sc1;
    g_a1[c]   = a1[c];
    g_s1[c]   = a1[c] / QLEV;

    float sc2 = g2[c] / sqrtf(v2[c] + EPSBN);
    g_bns2[c] = sc2;
    g_bnb2[c] = b2[c] - m2[c] * sc2;
    g_a2[c]   = a2[c];
    g_s2[c]   = a2[c] / QLEV;

    g_a3[c] = a3[c];
    g_s3[c] = a3[c] / QLEV;
}

// ---------------- implicit-GEMM 3x3 conv, fp32 FFMA ----------------
// block tile: 64 out-channels x (8x8 spatial), K chunked by 16 input channels.
// grid: (49 spatial tiles, 2 co-groups, 32 images), 256 threads.
template <int STAGE>
__global__ __launch_bounds__(256)
void conv_kernel(const float* __restrict__ in_p,
                 const float* __restrict__ xres,
                 float* __restrict__ out_p) {
    const int tile = blockIdx.x;
    const int th0  = (tile / 7) * 8;
    const int tw0  = (tile % 7) * 8;
    const int co0  = blockIdx.y * 64;
    const int n    = blockIdx.z;

    const float* in  = (STAGE == 1) ? in_p : g_act1;
    float*       dst = (STAGE == 1) ? g_act1 : out_p;
    const float* wq  = (STAGE == 1) ? g_w1t : g_w2t;

    __shared__ float sx[16][10][10];   // input halo tile (one 16-channel chunk)
    __shared__ float sw[144][64];      // weights [kc*9+rs][co]

    const int tx   = threadIdx.x;
    const int co_t = tx & 15;          // 16 co lanes
    const int sp_t = tx >> 4;          // 16 spatial groups of 4
    const int row  = sp_t >> 1;        // 0..7
    const int cb   = (sp_t & 1) * 4;   // 0 or 4

    float acc[4][4];
#pragma unroll
    for (int i = 0; i < 4; i++)
#pragma unroll
        for (int j = 0; j < 4; j++) acc[i][j] = 0.f;

    for (int ck = 0; ck < 8; ck++) {
        const int c0k = ck * 16;
        __syncthreads();
        // ---- load input halo tile (16 ch x 10 x 10) ----
        for (int i = tx; i < 1600; i += 256) {
            int kc  = i / 100, pos = i % 100;
            int hr  = th0 + pos / 10 - 1;
            int wc  = tw0 + pos % 10 - 1;
            float v = 0.f;
            if (hr >= 0 && hr < HIMG && wc >= 0 && wc < WIMG)
                v = in[(((size_t)n * CCH + c0k + kc) * HIMG + hr) * WIMG + wc];
            sx[kc][pos / 10][pos % 10] = v;
        }
        // ---- load weight tile (144 x 64), fully coalesced ----
        for (int i = tx; i < 144 * 64; i += 256) {
            int co = i & 63, t = i >> 6;
            sw[t][co] = wq[(size_t)(c0k * 9 + t) * CCH + co0 + co];
        }
        __syncthreads();

#pragma unroll 2
        for (int kc = 0; kc < 16; kc++) {
#pragma unroll
            for (int r = 0; r < 3; r++) {
                float xv[6];
#pragma unroll
                for (int u = 0; u < 6; u++) xv[u] = sx[kc][row + r][cb + u];
#pragma unroll
                for (int s = 0; s < 3; s++) {
                    float wv[4];
#pragma unroll
                    for (int i2 = 0; i2 < 4; i2++)
                        wv[i2] = sw[kc * 9 + r * 3 + s][co_t + 16 * i2];
#pragma unroll
                    for (int i2 = 0; i2 < 4; i2++)
#pragma unroll
                        for (int j = 0; j < 4; j++)
                            acc[i2][j] = fmaf(wv[i2], xv[s + j], acc[i2][j]);
                }
            }
        }
    }

    // ---- epilogue: BN + PACT (+ residual requant for stage 2) ----
#pragma unroll
    for (int i2 = 0; i2 < 4; i2++) {
        const int co = co0 + co_t + 16 * i2;
        float bns, bnb, aa, ss;
        if (STAGE == 1) { bns = g_bns1[co]; bnb = g_bnb1[co]; aa = g_a1[co]; ss = g_s1[co]; }
        else            { bns = g_bns2[co]; bnb = g_bnb2[co]; aa = g_a2[co]; ss = g_s2[co]; }
        const float a3v = g_a3[co];
        const float s3v = g_s3[co];
#pragma unroll
        for (int j = 0; j < 4; j++) {
            const int h = th0 + row, w = tw0 + cb + j;
            const size_t idx = (((size_t)n * CCH + co) * HIMG + h) * WIMG + w;
            float v  = acc[i2][j] * bns + bnb;
            float cl = fminf(fmaxf(v, 0.f), aa);
            float q  = rintf(cl / ss) * ss;          // PACT fake-quant (RNE like jnp.round)
            if (STAGE == 1) {
                dst[idx] = q;
            } else {
                float y  = rintf(q / s3v) * s3v + rintf(xres[idx] / s3v) * s3v;
                float yc = fminf(fmaxf(y, 0.f), a3v);
                dst[idx] = rintf(yc / s3v) * s3v;
            }
        }
    }
}

// ---------------- launch ----------------
extern "C" void kernel_launch(void* const* d_in, const int* in_sizes, int n_in,
                              void* d_out, int out_size) {
    const float* x  = (const float*)d_in[0];
    const float* w1 = (const float*)d_in[1];
    const float* g1 = (const float*)d_in[2];
    const float* b1 = (const float*)d_in[3];
    const float* m1 = (const float*)d_in[4];
    const float* v1 = (const float*)d_in[5];
    const float* a1 = (const float*)d_in[6];
    const float* w2 = (const float*)d_in[7];
    const float* g2 = (const float*)d_in[8];
    const float* b2 = (const float*)d_in[9];
    const float* m2 = (const float*)d_in[10];
    const float* v2 = (const float*)d_in[11];
    const float* a2 = (const float*)d_in[12];
    const float* a3 = (const float*)d_in[13];
    float* out = (float*)d_out;

    prep_weights<<<dim3(128, 2), 256>>>(w1, w2);
    prep_params<<<1, 128>>>(g1, b1, m1, v1, a1, g2, b2, m2, v2, a2, a3);

    dim3 grid(49, 2, 32);   // 7x7 spatial tiles, 2 co-groups of 64, 32 images
    conv_kernel<1><<<grid, 256>>>(x, nullptr, nullptr);  // -> g_act1
    conv_kernel<2><<<grid, 256>>>(nullptr, x, out);      // -> d_out
}

// round 2
// speedup vs baseline: 1.0116x; 1.0116x over previous
#include <cuda_runtime.h>
#include <math.h>

#define CCH   128
#define HIMG  56
#define WIMG  56
#define NIMG  32
#define EPSBN 1e-5f
#define QLEV  255.0f
#define WMAXQ 127.0f

// ---------------- device scratch (no runtime alloc allowed) ----------------
__device__ float g_w1t[CCH * 9 * CCH];                 // [(ci*9+rs)*CCH + co], fake-quantized
__device__ float g_w2t[CCH * 9 * CCH];
__device__ float g_act1[(size_t)NIMG * CCH * HIMG * WIMG]; // 51.4 MB intermediate
__device__ float g_bns1[CCH], g_bnb1[CCH], g_a1[CCH], g_s1[CCH];
__device__ float g_bns2[CCH], g_bnb2[CCH], g_a2[CCH], g_s2[CCH];
__device__ float g_a3[CCH],  g_s3[CCH];

// ---------------- weight fake-quant + transpose ----------------
// grid: (128 out-channels, 2 weight tensors), 256 threads
__global__ void prep_weights(const float* __restrict__ w1,
                             const float* __restrict__ w2) {
    const int o = blockIdx.x;
    const float* w  = (blockIdx.y == 0) ? w1 : w2;
    float* dst      = (blockIdx.y == 0) ? g_w1t : g_w2t;
    const float* wo = w + (size_t)o * CCH * 9;

    float m = 0.f;
    for (int i = threadIdx.x; i < CCH * 9; i += blockDim.x)
        m = fmaxf(m, fabsf(wo[i]));

    __shared__ float red[256];
    red[threadIdx.x] = m;
    __syncthreads();
    for (int s = 128; s > 0; s >>= 1) {
        if (threadIdx.x < s)
            red[threadIdx.x] = fmaxf(red[threadIdx.x], red[threadIdx.x + s]);
        __syncthreads();
    }
    const float scale = fmaxf(red[0] / WMAXQ, 1e-8f);

    for (int i = threadIdx.x; i < CCH * 9; i += blockDim.x) {
        float q = fminf(fmaxf(rintf(wo[i] / scale), -WMAXQ), WMAXQ) * scale;
        dst[(size_t)i * CCH + o] = q;   // i = ci*9 + rs  ->  [ci*9+rs][o]
    }
}

// ---------------- per-channel constant folding ----------------
__global__ void prep_params(const float* __restrict__ g1, const float* __restrict__ b1,
                            const float* __restrict__ m1, const float* __restrict__ v1,
                            const float* __restrict__ a1,
                            const float* __restrict__ g2, const float* __restrict__ b2,
                            const float* __restrict__ m2, const float* __restrict__ v2,
                            const float* __restrict__ a2,
                            const float* __restrict__ a3) {
    const int c = threadIdx.x;
    if (c >= CCH) return;
    float sc1 = g1[c] / sqrtf(v1[c] + EPSBN);
    g_bns1[c] = sc1;
    g_bnb1[c] = b1[c] - m1[c] * sc1;
    g_a1[c]   = a1[c];
    g_s1[c]   = a1[c] / QLEV;

    float sc2 = g2[c] / sqrtf(v2[c] + EPSBN);
    g_bns2[c] = sc2;
    g_bnb2[c] = b2[c] - m2[c] * sc2;
    g_a2[c]   = a2[c];
    g_s2[c]   = a2[c] / QLEV;

    g_a3[c] = a3[c];
    g_s3[c] = a3[c] / QLEV;
}

// ---------------- implicit-GEMM 3x3 conv, fp32 FFMA ----------------
// block tile: 64 out-channels x (8x8 spatial), K chunked by 16 input channels.
// grid: (49 spatial tiles, 2 co-groups, 32 images), 256 threads.
template <int STAGE>
__global__ __launch_bounds__(256)
void conv_kernel(const float* __restrict__ in_p,
                 const float* __restrict__ xres,
                 float* __restrict__ out_p) {
    const int tile = blockIdx.x;
    const int th0  = (tile / 7) * 8;
    const int tw0  = (tile % 7) * 8;
    const int co0  = blockIdx.y * 64;
    const int n    = blockIdx.z;

    const float* in  = (STAGE == 1) ? in_p : g_act1;
    float*       dst = (STAGE == 1) ? g_act1 : out_p;
    const float* wq  = (STAGE == 1) ? g_w1t : g_w2t;

    __shared__ float sx[16][10][10];   // input halo tile (one 16-channel chunk)
    __shared__ float sw[144][64];      // weights [kc*9+rs][co]

    const int tx   = threadIdx.x;
    const int co_t = tx & 15;          // 16 co lanes
    const int sp_t = tx >> 4;          // 16 spatial groups of 4
    const int row  = sp_t >> 1;        // 0..7
    const int cb   = (sp_t & 1) * 4;   // 0 or 4

    float acc[4][4];
#pragma unroll
    for (int i = 0; i < 4; i++)
#pragma unroll
        for (int j = 0; j < 4; j++) acc[i][j] = 0.f;

    for (int ck = 0; ck < 8; ck++) {
        const int c0k = ck * 16;
        __syncthreads();
        // ---- load input halo tile (16 ch x 10 x 10) ----
        for (int i = tx; i < 1600; i += 256) {
            int kc  = i / 100, pos = i % 100;
            int hr  = th0 + pos / 10 - 1;
            int wc  = tw0 + pos % 10 - 1;
            float v = 0.f;
            if (hr >= 0 && hr < HIMG && wc >= 0 && wc < WIMG)
                v = in[(((size_t)n * CCH + c0k + kc) * HIMG + hr) * WIMG + wc];
            sx[kc][pos / 10][pos % 10] = v;
        }
        // ---- load weight tile (144 x 64), fully coalesced ----
        for (int i = tx; i < 144 * 64; i += 256) {
            int co = i & 63, t = i >> 6;
            sw[t][co] = wq[(size_t)(c0k * 9 + t) * CCH + co0 + co];
        }
        __syncthreads();

#pragma unroll 2
        for (int kc = 0; kc < 16; kc++) {
#pragma unroll
            for (int r = 0; r < 3; r++) {
                float xv[6];
#pragma unroll
                for (int u = 0; u < 6; u++) xv[u] = sx[kc][row + r][cb + u];
#pragma unroll
                for (int s = 0; s < 3; s++) {
                    float wv[4];
#pragma unroll
                    for (int i2 = 0; i2 < 4; i2++)
                        wv[i2] = sw[kc * 9 + r * 3 + s][co_t + 16 * i2];
#pragma unroll
                    for (int i2 = 0; i2 < 4; i2++)
#pragma unroll
                        for (int j = 0; j < 4; j++)
                            acc[i2][j] = fmaf(wv[i2], xv[s + j], acc[i2][j]);
                }
            }
        }
    }

    // ---- epilogue: BN + PACT (+ residual requant for stage 2) ----
#pragma unroll
    for (int i2 = 0; i2 < 4; i2++) {
        const int co = co0 + co_t + 16 * i2;
        float bns, bnb, aa, ss;
        if (STAGE == 1) { bns = g_bns1[co]; bnb = g_bnb1[co]; aa = g_a1[co]; ss = g_s1[co]; }
        else            { bns = g_bns2[co]; bnb = g_bnb2[co]; aa = g_a2[co]; ss = g_s2[co]; }
        const float a3v = g_a3[co];
        const float s3v = g_s3[co];
#pragma unroll
        for (int j = 0; j < 4; j++) {
            const int h = th0 + row, w = tw0 + cb + j;
            const size_t idx = (((size_t)n * CCH + co) * HIMG + h) * WIMG + w;
            float v  = acc[i2][j] * bns + bnb;
            float cl = fminf(fmaxf(v, 0.f), aa);
            float q  = rintf(cl / ss) * ss;          // PACT fake-quant (RNE like jnp.round)
            if (STAGE == 1) {
                dst[idx] = q;
            } else {
                float y  = rintf(q / s3v) * s3v + rintf(xres[idx] / s3v) * s3v;
                float yc = fminf(fmaxf(y, 0.f), a3v);
                dst[idx] = rintf(yc / s3v) * s3v;
            }
        }
    }
}

// ---------------- launch ----------------
extern "C" void kernel_launch(void* const* d_in, const int* in_sizes, int n_in,
                              void* d_out, int out_size) {
    const float* x  = (const float*)d_in[0];
    const float* w1 = (const float*)d_in[1];
    const float* g1 = (const float*)d_in[2];
    const float* b1 = (const float*)d_in[3];
    const float* m1 = (const float*)d_in[4];
    const float* v1 = (const float*)d_in[5];
    const float* a1 = (const float*)d_in[6];
    const float* w2 = (const float*)d_in[7];
    const float* g2 = (const float*)d_in[8];
    const float* b2 = (const float*)d_in[9];
    const float* m2 = (const float*)d_in[10];
    const float* v2 = (const float*)d_in[11];
    const float* a2 = (const float*)d_in[12];
    const float* a3 = (const float*)d_in[13];
    float* out = (float*)d_out;

    prep_weights<<<dim3(128, 2), 256>>>(w1, w2);
    prep_params<<<1, 128>>>(g1, b1, m1, v1, a1, g2, b2, m2, v2, a2, a3);

    dim3 grid(49, 2, 32);   // 7x7 spatial tiles, 2 co-groups of 64, 32 images
    conv_kernel<1><<<grid, 256>>>(x, nullptr, nullptr);  // -> g_act1
    conv_kernel<2><<<grid, 256>>>(nullptr, x, out);      // -> d_out
}

// round 4
// speedup vs baseline: 1.7658x; 1.7456x over previous
#include <cuda_runtime.h>
#include <cuda_fp16.h>
#include <math.h>
#include <stdint.h>

#define CCH   128
#define HIMG  56
#define WIMG  56
#define NIMG  32
#define EPSBN 1e-5f
#define QLEV  255.0f
#define WMAXQ 127.0f

#define NPIX ((size_t)NIMG * CCH * HIMG * WIMG)

// ---------------- device scratch ----------------
// activations packed [n][ck8][h][w][ci16], hi/lo fp16 split
__device__ unsigned short g_xhi[NPIX],  g_xlo[NPIX];
__device__ unsigned short g_a1hi[NPIX], g_a1lo[NPIX];
// weights packed [ck8][rs9][co128][ci16], hi/lo split
#define WELEMS (8 * 9 * 128 * 16)
__device__ unsigned short g_w1hi[WELEMS], g_w1lo[WELEMS];
__device__ unsigned short g_w2hi[WELEMS], g_w2lo[WELEMS];
__device__ float g_bns1[CCH], g_bnb1[CCH], g_a1p[CCH], g_s1[CCH];
__device__ float g_bns2[CCH], g_bnb2[CCH], g_a2p[CCH], g_s2[CCH];
__device__ float g_a3p[CCH], g_s3[CCH];

// ---------------- PTX helpers (sm_80-class only: valid for target sm_100) ----
__device__ __forceinline__ uint32_t smem_u32(const void* p) {
    uint32_t a;
    asm("{ .reg .u64 t; cvta.to.shared.u64 t, %1; cvt.u32.u64 %0, t; }" : "=r"(a) : "l"(p));
    return a;
}

__device__ __forceinline__ void cp16(uint32_t dst, const void* src, int sz) {
    asm volatile("cp.async.cg.shared.global [%0], [%1], 16, %2;"
                 :: "r"(dst), "l"(__cvta_generic_to_global(src)), "r"(sz) : "memory");
}
__device__ __forceinline__ void cp_commit() {
    asm volatile("cp.async.commit_group;" ::: "memory");
}
template <int N> __device__ __forceinline__ void cp_wait() {
    asm volatile("cp.async.wait_group %0;" :: "n"(N) : "memory");
}

__device__ __forceinline__ void ldsm4(uint32_t r[4], uint32_t addr) {
    asm volatile("ldmatrix.sync.aligned.m8n8.x4.shared.b16 {%0,%1,%2,%3}, [%4];"
                 : "=r"(r[0]), "=r"(r[1]), "=r"(r[2]), "=r"(r[3]) : "r"(addr));
}

__device__ __forceinline__ void mma16816(float d[4], const uint32_t a[4],
                                         uint32_t b0, uint32_t b1) {
    asm volatile("mma.sync.aligned.m16n8k16.row.col.f32.f16.f16.f32 "
                 "{%0,%1,%2,%3}, {%4,%5,%6,%7}, {%8,%9}, {%0,%1,%2,%3};"
                 : "+f"(d[0]), "+f"(d[1]), "+f"(d[2]), "+f"(d[3])
                 : "r"(a[0]), "r"(a[1]), "r"(a[2]), "r"(a[3]), "r"(b0), "r"(b1));
}

// ---------------- prep kernels ----------------
__global__ void presplit_x(const float* __restrict__ x) {
    for (size_t i = (size_t)blockIdx.x * blockDim.x + threadIdx.x; i < NPIX;
         i += (size_t)gridDim.x * blockDim.x) {
        int w = (int)(i % 56);
        int h = (int)((i / 56) % 56);
        int c = (int)((i / 3136) % 128);
        int n = (int)(i / (3136 * 128));
        float v = x[i];
        __half hh = __float2half_rn(v);
        __half ll = __float2half_rn((v - __half2float(hh)) * 2048.0f);
        size_t d = ((((size_t)n * 8 + (c >> 4)) * 56 + h) * 56 + w) * 16 + (c & 15);
        g_xhi[d] = __half_as_ushort(hh);
        g_xlo[d] = __half_as_ushort(ll);
    }
}

__global__ void prep_weights(const float* __restrict__ w1, const float* __restrict__ w2) {
    const int o = blockIdx.x;
    const float* w = (blockIdx.y == 0) ? w1 : w2;
    unsigned short* dhi = (blockIdx.y == 0) ? g_w1hi : g_w2hi;
    unsigned short* dlo = (blockIdx.y == 0) ? g_w1lo : g_w2lo;
    const float* wo = w + (size_t)o * CCH * 9;

    float m = 0.f;
    for (int i = threadIdx.x; i < CCH * 9; i += blockDim.x)
        m = fmaxf(m, fabsf(wo[i]));
    __shared__ float red[256];
    red[threadIdx.x] = m;
    __syncthreads();
    for (int s = 128; s > 0; s >>= 1) {
        if (threadIdx.x < s) red[threadIdx.x] = fmaxf(red[threadIdx.x], red[threadIdx.x + s]);
        __syncthreads();
    }
    const float scale = fmaxf(red[0] / WMAXQ, 1e-8f);

    for (int i = threadIdx.x; i < CCH * 9; i += blockDim.x) {
        int ci = i / 9, rs = i % 9;
        float q = fminf(fmaxf(rintf(wo[i] / scale), -WMAXQ), WMAXQ) * scale;
        __half hh = __float2half_rn(q);
        __half ll = __float2half_rn((q - __half2float(hh)) * 2048.0f);
        size_t d = ((size_t)(((ci >> 4) * 9 + rs) * 128 + o) << 4) + (ci & 15);
        dhi[d] = __half_as_ushort(hh);
        dlo[d] = __half_as_ushort(ll);
    }
}

__global__ void prep_params(const float* g1, const float* b1, const float* m1, const float* v1,
                            const float* a1, const float* g2, const float* b2, const float* m2,
                            const float* v2, const float* a2, const float* a3) {
    const int c = threadIdx.x;
    if (c >= CCH) return;
    float sc1 = g1[c] / sqrtf(v1[c] + EPSBN);
    g_bns1[c] = sc1; g_bnb1[c] = b1[c] - m1[c] * sc1; g_a1p[c] = a1[c]; g_s1[c] = a1[c] / QLEV;
    float sc2 = g2[c] / sqrtf(v2[c] + EPSBN);
    g_bns2[c] = sc2; g_bnb2[c] = b2[c] - m2[c] * sc2; g_a2p[c] = a2[c]; g_s2[c] = a2[c] / QLEV;
    g_a3p[c] = a3[c]; g_s3[c] = a3[c] / QLEV;
}

// ---------------- smem layout per buffer ----------------
// [0,3200)      halo hi : 100 px * 32B  ([h10][w10][ci16])
// [3200,6400)   halo lo
// [6400,43264)  weights hi : [rs9][co128][ci16] = 36864B
// [43264,80128) weights lo
#define BUFSZ  80128
#define SMTOT  (2 * BUFSZ)

// ---------------- fused conv stage (mma.sync fp16 split-precision) ----------
template <int STAGE>
__global__ void __launch_bounds__(256, 1)
conv_mma(const float* __restrict__ x_res, float* __restrict__ out) {
    extern __shared__ char smem[];
    const uint32_t sb = smem_u32(smem);

    const int tid   = threadIdx.x;
    const int lane  = tid & 31;
    const int wid   = tid >> 5;
    const int warpM = wid & 3;      // 4 warps over M (pixels)
    const int warpN = wid >> 2;     // 2 warps over N (co)

    const int w0 = blockIdx.x * 8;
    const int h0 = blockIdx.y * 8;
    const int n  = blockIdx.z;

    const unsigned short* __restrict__ srcHi = (STAGE == 1) ? g_xhi : g_a1hi;
    const unsigned short* __restrict__ srcLo = (STAGE == 1) ? g_xlo : g_a1lo;
    const unsigned short* __restrict__ wHi   = (STAGE == 1) ? g_w1hi : g_w2hi;
    const unsigned short* __restrict__ wLo   = (STAGE == 1) ? g_w1lo : g_w2lo;

    // ---- per-lane ldmatrix address components ----
    // A (m16k16): row = lane&15 -> pixel, khalf = lane>>4
    const int arow  = lane & 15;
    const int ph    = (warpM * 16 + arow) >> 3;   // 0..7
    const int pw    = (warpM * 16 + arow) & 7;    // 0..7
    const int akh   = (lane >> 4) * 16;
    // B (k16n8 pairs): g = lane>>3: coL=(g>>1)*8+(lane&7), khB=g&1
    const int bg    = lane >> 3;
    const int coL   = ((bg >> 1) << 3) + (lane & 7);
    const int bkh   = (bg & 1) * 16;
    uint32_t bAddrBase[4];
#pragma unroll
    for (int t = 0; t < 4; t++) {
        int co = warpN * 64 + t * 16 + coL;
        bAddrBase[t] = 6400u + co * 32 + (uint32_t)(bkh ^ (((coL >> 2) & 1) * 16));
    }

    // ---- async-load helper ----
    auto issue_chunk = [&](int ck, int buf) {
        const uint32_t bufo = sb + buf * BUFSZ;
        // halo: 400 x 16B
        for (int e = tid; e < 400; e += 256) {
            int pix = e >> 2, split = (e >> 1) & 1, half = e & 1;
            int hh = pix / 10, ww = pix % 10;
            int hg = h0 - 1 + hh, wg = w0 - 1 + ww;
            bool inb = (hg >= 0) & (hg < HIMG) & (wg >= 0) & (wg < WIMG);
            size_t elem = inb ? (((((size_t)n * 8 + ck) * 56 + hg) * 56 + wg) * 16 + half * 8) : 0;
            const unsigned short* s = (split ? srcLo : srcHi) + elem;
            uint32_t d = bufo + split * 3200 +
                         (uint32_t)((pix * 32 + half * 16) ^ ((ww & 4) << 2));
            cp16(d, s, inb ? 16 : 0);
        }
        // weights: 4608 x 16B (split 0: e<2304 hi, else lo), linear copy + swizzle
        for (int e = tid; e < 4608; e += 256) {
            int split = (e >= 2304);
            int e2 = e - split * 2304;
            const unsigned short* s = (split ? wLo : wHi) + (size_t)ck * 18432 + e2 * 8;
            uint32_t d = bufo + 6400 + split * 36864 +
                         (uint32_t)((e2 * 16) ^ ((e2 & 8) << 1));
            cp16(d, s, 16);
        }
        cp_commit();
    };

    float D0[8][4], D1[8][4];
#pragma unroll
    for (int f = 0; f < 8; f++)
#pragma unroll
        for (int j = 0; j < 4; j++) { D0[f][j] = 0.f; D1[f][j] = 0.f; }

    issue_chunk(0, 0);

    for (int ck = 0; ck < 8; ck++) {
        if (ck < 7) issue_chunk(ck + 1, (ck + 1) & 1);
        if (ck < 7) cp_wait<1>(); else cp_wait<0>();
        __syncthreads();

        const uint32_t sbuf = sb + (ck & 1) * BUFSZ;
#pragma unroll 3
        for (int rs = 0; rs < 9; rs++) {
            const int r = rs / 3, s = rs % 3;
            // A fragments
            const int wcol = pw + s;
            uint32_t aaddr = sbuf + (uint32_t)(((ph + r) * 10 + wcol) * 32) +
                             (uint32_t)(akh ^ (((wcol >> 2) & 1) * 16));
            uint32_t ah[4], al[4];
            ldsm4(ah, aaddr);
            ldsm4(al, aaddr + 3200);
            // B fragments
            const uint32_t bbase = sbuf + rs * 4096;
            uint32_t bh[4][4], bl[4][4];
#pragma unroll
            for (int t = 0; t < 4; t++) {
                ldsm4(bh[t], bbase + bAddrBase[t]);
                ldsm4(bl[t], bbase + bAddrBase[t] + 36864);
            }
            // 3-pass split-precision MMA
#pragma unroll
            for (int f = 0; f < 8; f++) {
                const int t = f >> 1, o = (f & 1) * 2;
                mma16816(D0[f], ah, bh[t][o], bh[t][o + 1]);
                mma16816(D1[f], ah, bl[t][o], bl[t][o + 1]);
                mma16816(D1[f], al, bh[t][o], bh[t][o + 1]);
            }
        }
        __syncthreads();
    }

    // ---------------- epilogue ----------------
    const int qrow = lane >> 2;
    const int rr   = lane & 3;
    const float inv2048 = 1.0f / 2048.0f;

#pragma unroll
    for (int f = 0; f < 8; f++) {
        const int coB = warpN * 64 + (f >> 1) * 16 + (f & 1) * 8;
#pragma unroll
        for (int j = 0; j < 4; j++) {
            const int co = coB + 2 * rr + (j & 1);
            const int p  = warpM * 16 + qrow + (j >> 1) * 8;
            const int h  = h0 + (p >> 3);
            const int w  = w0 + (p & 7);
            float d = D0[f][j] + D1[f][j] * inv2048;
            if (STAGE == 1) {
                float v  = d * g_bns1[co] + g_bnb1[co];
                float cl = fminf(fmaxf(v, 0.f), g_a1p[co]);
                float ss = g_s1[co];
                float qv = rintf(cl / ss) * ss;
                __half hq = __float2half_rn(qv);
                __half lq = __float2half_rn((qv - __half2float(hq)) * 2048.0f);
                size_t idx = ((((size_t)n * 8 + (co >> 4)) * 56 + h) * 56 + w) * 16 + (co & 15);
                g_a1hi[idx] = __half_as_ushort(hq);
                g_a1lo[idx] = __half_as_ushort(lq);
            } else {
                float v  = d * g_bns2[co] + g_bnb2[co];
                float cl = fminf(fmaxf(v, 0.f), g_a2p[co]);
                float ss = g_s2[co];
                float qv = rintf(cl / ss) * ss;
                float s3 = g_s3[co];
                size_t idx2 = (((size_t)n * 128 + co) * 56 + h) * 56 + w;
                float y  = rintf(qv / s3) * s3 + rintf(x_res[idx2] / s3) * s3;
                float yc = fminf(fmaxf(y, 0.f), g_a3p[co]);
                out[idx2] = rintf(yc / s3) * s3;
            }
        }
    }
}

// ---------------- launch ----------------
extern "C" void kernel_launch(void* const* d_in, const int* in_sizes, int n_in,
                              void* d_out, int out_size) {
    const float* x  = (const float*)d_in[0];
    const float* w1 = (const float*)d_in[1];
    const float* g1 = (const float*)d_in[2];
    const float* b1 = (const float*)d_in[3];
    const float* m1 = (const float*)d_in[4];
    const float* v1 = (const float*)d_in[5];
    const float* a1 = (const float*)d_in[6];
    const float* w2 = (const float*)d_in[7];
    const float* g2 = (const float*)d_in[8];
    const float* b2 = (const float*)d_in[9];
    const float* m2 = (const float*)d_in[10];
    const float* v2 = (const float*)d_in[11];
    const float* a2 = (const float*)d_in[12];
    const float* a3 = (const float*)d_in[13];
    float* out = (float*)d_out;

    cudaFuncSetAttribute(conv_mma<1>, cudaFuncAttributeMaxDynamicSharedMemorySize, SMTOT);
    cudaFuncSetAttribute(conv_mma<2>, cudaFuncAttributeMaxDynamicSharedMemorySize, SMTOT);

    presplit_x<<<2048, 256>>>(x);
    prep_weights<<<dim3(128, 2), 256>>>(w1, w2);
    prep_params<<<1, 128>>>(g1, b1, m1, v1, a1, g2, b2, m2, v2, a2, a3);

    dim3 grid(7, 7, 32);
    conv_mma<1><<<grid, 256, SMTOT>>>(nullptr, nullptr);
    conv_mma<2><<<grid, 256, SMTOT>>>(x, out);
}

// round 5
// speedup vs baseline: 2.3533x; 1.3327x over previous
#include <cuda_runtime.h>
#include <cuda_fp16.h>
#include <math.h>
#include <stdint.h>

#define CCH   128
#define HIMG  56
#define WIMG  56
#define NIMG  32
#define EPSBN 1e-5f
#define QLEV  255.0f
#define WMAXQ 127.0f

#define NPIX ((size_t)NIMG * CCH * HIMG * WIMG)

// ---------------- device scratch ----------------
// activations packed [n][ck8][h][w][ci16], hi/lo fp16 split
__device__ unsigned short g_xhi[NPIX],  g_xlo[NPIX];
__device__ unsigned short g_a1hi[NPIX], g_a1lo[NPIX];
// weights packed [ck8][rs9][co128][ci16], hi/lo split
#define WELEMS (8 * 9 * 128 * 16)
__device__ unsigned short g_w1hi[WELEMS], g_w1lo[WELEMS];
__device__ unsigned short g_w2hi[WELEMS], g_w2lo[WELEMS];
__device__ float g_bns1[CCH], g_bnb1[CCH], g_a1p[CCH], g_s1[CCH];
__device__ float g_bns2[CCH], g_bnb2[CCH], g_a2p[CCH], g_s2[CCH];
__device__ float g_a3p[CCH], g_s3[CCH];

// ---------------- PTX helpers (sm_80-class, valid for target sm_100) ------
__device__ __forceinline__ uint32_t smem_u32(const void* p) {
    uint32_t a;
    asm("{ .reg .u64 t; cvta.to.shared.u64 t, %1; cvt.u32.u64 %0, t; }" : "=r"(a) : "l"(p));
    return a;
}

__device__ __forceinline__ void cp16(uint32_t dst, const void* src, int sz) {
    asm volatile("cp.async.cg.shared.global [%0], [%1], 16, %2;"
                 :: "r"(dst), "l"(__cvta_generic_to_global(src)), "r"(sz) : "memory");
}
__device__ __forceinline__ void cp_commit() {
    asm volatile("cp.async.commit_group;" ::: "memory");
}
template <int N> __device__ __forceinline__ void cp_wait() {
    asm volatile("cp.async.wait_group %0;" :: "n"(N) : "memory");
}

__device__ __forceinline__ void ldsm4(uint32_t r[4], uint32_t addr) {
    asm volatile("ldmatrix.sync.aligned.m8n8.x4.shared.b16 {%0,%1,%2,%3}, [%4];"
                 : "=r"(r[0]), "=r"(r[1]), "=r"(r[2]), "=r"(r[3]) : "r"(addr));
}

__device__ __forceinline__ void mma16816(float d[4], const uint32_t a[4],
                                         uint32_t b0, uint32_t b1) {
    asm volatile("mma.sync.aligned.m16n8k16.row.col.f32.f16.f16.f32 "
                 "{%0,%1,%2,%3}, {%4,%5,%6,%7}, {%8,%9}, {%0,%1,%2,%3};"
                 : "+f"(d[0]), "+f"(d[1]), "+f"(d[2]), "+f"(d[3])
                 : "r"(a[0]), "r"(a[1]), "r"(a[2]), "r"(a[3]), "r"(b0), "r"(b1));
}

// ---------------- prep kernels ----------------
__global__ void presplit_x(const float* __restrict__ x) {
    for (size_t i = (size_t)blockIdx.x * blockDim.x + threadIdx.x; i < NPIX;
         i += (size_t)gridDim.x * blockDim.x) {
        int w = (int)(i % 56);
        int h = (int)((i / 56) % 56);
        int c = (int)((i / 3136) % 128);
        int n = (int)(i / (3136 * 128));
        float v = x[i];
        __half hh = __float2half_rn(v);
        __half ll = __float2half_rn((v - __half2float(hh)) * 2048.0f);
        size_t d = ((((size_t)n * 8 + (c >> 4)) * 56 + h) * 56 + w) * 16 + (c & 15);
        g_xhi[d] = __half_as_ushort(hh);
        g_xlo[d] = __half_as_ushort(ll);
    }
}

__global__ void prep_weights(const float* __restrict__ w1, const float* __restrict__ w2) {
    const int o = blockIdx.x;
    const float* w = (blockIdx.y == 0) ? w1 : w2;
    unsigned short* dhi = (blockIdx.y == 0) ? g_w1hi : g_w2hi;
    unsigned short* dlo = (blockIdx.y == 0) ? g_w1lo : g_w2lo;
    const float* wo = w + (size_t)o * CCH * 9;

    float m = 0.f;
    for (int i = threadIdx.x; i < CCH * 9; i += blockDim.x)
        m = fmaxf(m, fabsf(wo[i]));
    __shared__ float red[256];
    red[threadIdx.x] = m;
    __syncthreads();
    for (int s = 128; s > 0; s >>= 1) {
        if (threadIdx.x < s) red[threadIdx.x] = fmaxf(red[threadIdx.x], red[threadIdx.x + s]);
        __syncthreads();
    }
    const float scale = fmaxf(red[0] / WMAXQ, 1e-8f);

    for (int i = threadIdx.x; i < CCH * 9; i += blockDim.x) {
        int ci = i / 9, rs = i % 9;
        float q = fminf(fmaxf(rintf(wo[i] / scale), -WMAXQ), WMAXQ) * scale;
        __half hh = __float2half_rn(q);
        __half ll = __float2half_rn((q - __half2float(hh)) * 2048.0f);
        size_t d = ((size_t)(((ci >> 4) * 9 + rs) * 128 + o) << 4) + (ci & 15);
        dhi[d] = __half_as_ushort(hh);
        dlo[d] = __half_as_ushort(ll);
    }
}

__global__ void prep_params(const float* g1, const float* b1, const float* m1, const float* v1,
                            const float* a1, const float* g2, const float* b2, const float* m2,
                            const float* v2, const float* a2, const float* a3) {
    const int c = threadIdx.x;
    if (c >= CCH) return;
    float sc1 = g1[c] / sqrtf(v1[c] + EPSBN);
    g_bns1[c] = sc1; g_bnb1[c] = b1[c] - m1[c] * sc1; g_a1p[c] = a1[c]; g_s1[c] = a1[c] / QLEV;
    float sc2 = g2[c] / sqrtf(v2[c] + EPSBN);
    g_bns2[c] = sc2; g_bnb2[c] = b2[c] - m2[c] * sc2; g_a2p[c] = a2[c]; g_s2[c] = a2[c] / QLEV;
    g_a3p[c] = a3[c]; g_s3[c] = a3[c] / QLEV;
}

// ---------------- smem layout per buffer ----------------
// [0,3200)       halo hi : 100 px * 32B  ([h10][w10][ci16])
// [3200,6400)    halo lo
// [6400,24832)   weights hi : [rs9][co64][ci16] = 18432B
// [24832,43264)  weights lo
#define WBYTES 18432
#define BUFSZ  43264
#define SMTOT  (2 * BUFSZ)

// ---------------- fused conv stage (mma.sync fp16 split-precision) --------
// CTA: 64 pixels (8x8) x 64 out-channels. 2 CTAs co-resident per SM.
template <int STAGE>
__global__ void __launch_bounds__(256, 2)
conv_mma(const float* __restrict__ x_res, float* __restrict__ out) {
    extern __shared__ char smem[];
    const uint32_t sb = smem_u32(smem);

    const int tid   = threadIdx.x;
    const int lane  = tid & 31;
    const int wid   = tid >> 5;
    const int warpM = wid & 3;      // 4 warps over M (pixels)
    const int warpN = wid >> 2;     // 2 warps over N (32 co each)

    const int w0  = (blockIdx.x >> 1) * 8;
    const int co0 = (blockIdx.x & 1) * 64;
    const int h0  = blockIdx.y * 8;
    const int n   = blockIdx.z;

    const unsigned short* __restrict__ srcHi = (STAGE == 1) ? g_xhi : g_a1hi;
    const unsigned short* __restrict__ srcLo = (STAGE == 1) ? g_xlo : g_a1lo;
    const unsigned short* __restrict__ wHi   = (STAGE == 1) ? g_w1hi : g_w2hi;
    const unsigned short* __restrict__ wLo   = (STAGE == 1) ? g_w1lo : g_w2lo;

    // ---- per-lane ldmatrix address components ----
    const int arow  = lane & 15;
    const int ph    = (warpM * 16 + arow) >> 3;   // 0..7
    const int pw    = (warpM * 16 + arow) & 7;    // 0..7
    const int akh   = (lane >> 4) * 16;
    const int bg    = lane >> 3;
    const int coL   = ((bg >> 1) << 3) + (lane & 7);
    const int bkh   = (bg & 1) * 16;
    uint32_t bAddrBase[2];
#pragma unroll
    for (int t = 0; t < 2; t++) {
        int co = warpN * 32 + t * 16 + coL;      // local co 0..63
        bAddrBase[t] = 6400u + co * 32 + (uint32_t)(bkh ^ (((coL >> 2) & 1) * 16));
    }

    // ---- async-load helper ----
    auto issue_chunk = [&](int ck, int buf) {
        const uint32_t bufo = sb + buf * BUFSZ;
        // halo: 400 x 16B
        for (int e = tid; e < 400; e += 256) {
            int pix = e >> 2, split = (e >> 1) & 1, half = e & 1;
            int hh = pix / 10, ww = pix % 10;
            int hg = h0 - 1 + hh, wg = w0 - 1 + ww;
            bool inb = (hg >= 0) & (hg < HIMG) & (wg >= 0) & (wg < WIMG);
            size_t elem = inb ? (((((size_t)n * 8 + ck) * 56 + hg) * 56 + wg) * 16 + half * 8) : 0;
            const unsigned short* s = (split ? srcLo : srcHi) + elem;
            uint32_t d = bufo + split * 3200 +
                         (uint32_t)((pix * 32 + half * 16) ^ ((ww & 4) << 2));
            cp16(d, s, inb ? 16 : 0);
        }
        // weights: 2304 x 16B (split: e<1152 hi, else lo)
        for (int e = tid; e < 2304; e += 256) {
            int split = (e >= 1152);
            int e2 = e - split * 1152;           // = rs*128 + u
            int rs = e2 >> 7, u = e2 & 127;      // u = co_local*2 + half
            const unsigned short* s = (split ? wLo : wHi) +
                (size_t)ck * 18432 + rs * 2048 + co0 * 16 + u * 8;
            uint32_t d = bufo + 6400 + split * WBYTES +
                         (uint32_t)((e2 * 16) ^ ((e2 & 8) << 1));
            cp16(d, s, 16);
        }
        cp_commit();
    };

    float D0[4][4], D1[4][4];
#pragma unroll
    for (int f = 0; f < 4; f++)
#pragma unroll
        for (int j = 0; j < 4; j++) { D0[f][j] = 0.f; D1[f][j] = 0.f; }

    issue_chunk(0, 0);

    for (int ck = 0; ck < 8; ck++) {
        if (ck < 7) issue_chunk(ck + 1, (ck + 1) & 1);
        if (ck < 7) cp_wait<1>(); else cp_wait<0>();
        __syncthreads();

        const uint32_t sbuf = sb + (ck & 1) * BUFSZ;
#pragma unroll 3
        for (int rs = 0; rs < 9; rs++) {
            const int r = rs / 3, s = rs % 3;
            // A fragments
            const int wcol = pw + s;
            uint32_t aaddr = sbuf + (uint32_t)(((ph + r) * 10 + wcol) * 32) +
                             (uint32_t)(akh ^ (((wcol >> 2) & 1) * 16));
            uint32_t ah[4], al[4];
            ldsm4(ah, aaddr);
            ldsm4(al, aaddr + 3200);
            // B fragments (rs block stride = 64co * 32B = 2048)
            const uint32_t bbase = sbuf + rs * 2048;
            uint32_t bh[2][4], bl[2][4];
#pragma unroll
            for (int t = 0; t < 2; t++) {
                ldsm4(bh[t], bbase + bAddrBase[t]);
                ldsm4(bl[t], bbase + bAddrBase[t] + WBYTES);
            }
            // 3-pass split-precision MMA
#pragma unroll
            for (int f = 0; f < 4; f++) {
                const int t = f >> 1, o = (f & 1) * 2;
                mma16816(D0[f], ah, bh[t][o], bh[t][o + 1]);
                mma16816(D1[f], ah, bl[t][o], bl[t][o + 1]);
                mma16816(D1[f], al, bh[t][o], bh[t][o + 1]);
            }
        }
        __syncthreads();
    }

    // ---------------- epilogue ----------------
    const int qrow = lane >> 2;
    const int rr   = lane & 3;
    const float inv2048 = 1.0f / 2048.0f;

#pragma unroll
    for (int f = 0; f < 4; f++) {
        const int coB = co0 + warpN * 32 + (f >> 1) * 16 + (f & 1) * 8;
#pragma unroll
        for (int j = 0; j < 4; j++) {
            const int co = coB + 2 * rr + (j & 1);
            const int p  = warpM * 16 + qrow + (j >> 1) * 8;
            const int h  = h0 + (p >> 3);
            const int w  = w0 + (p & 7);
            float d = D0[f][j] + D1[f][j] * inv2048;
            if (STAGE == 1) {
                float v  = d * g_bns1[co] + g_bnb1[co];
                float cl = fminf(fmaxf(v, 0.f), g_a1p[co]);
                float ss = g_s1[co];
                float qv = rintf(cl / ss) * ss;
                __half hq = __float2half_rn(qv);
                __half lq = __float2half_rn((qv - __half2float(hq)) * 2048.0f);
                size_t idx = ((((size_t)n * 8 + (co >> 4)) * 56 + h) * 56 + w) * 16 + (co & 15);
                g_a1hi[idx] = __half_as_ushort(hq);
                g_a1lo[idx] = __half_as_ushort(lq);
            } else {
                float v  = d * g_bns2[co] + g_bnb2[co];
                float cl = fminf(fmaxf(v, 0.f), g_a2p[co]);
                float ss = g_s2[co];
                float qv = rintf(cl / ss) * ss;
                float s3 = g_s3[co];
                size_t idx2 = (((size_t)n * 128 + co) * 56 + h) * 56 + w;
                float y  = rintf(qv / s3) * s3 + rintf(x_res[idx2] / s3) * s3;
                float yc = fminf(fmaxf(y, 0.f), g_a3p[co]);
                out[idx2] = rintf(yc / s3) * s3;
            }
        }
    }
}

// ---------------- launch ----------------
extern "C" void kernel_launch(void* const* d_in, const int* in_sizes, int n_in,
                              void* d_out, int out_size) {
    const float* x  = (const float*)d_in[0];
    const float* w1 = (const float*)d_in[1];
    const float* g1 = (const float*)d_in[2];
    const float* b1 = (const float*)d_in[3];
    const float* m1 = (const float*)d_in[4];
    const float* v1 = (const float*)d_in[5];
    const float* a1 = (const float*)d_in[6];
    const float* w2 = (const float*)d_in[7];
    const float* g2 = (const float*)d_in[8];
    const float* b2 = (const float*)d_in[9];
    const float* m2 = (const float*)d_in[10];
    const float* v2 = (const float*)d_in[11];
    const float* a2 = (const float*)d_in[12];
    const float* a3 = (const float*)d_in[13];
    float* out = (float*)d_out;

    cudaFuncSetAttribute(conv_mma<1>, cudaFuncAttributeMaxDynamicSharedMemorySize, SMTOT);
    cudaFuncSetAttribute(conv_mma<2>, cudaFuncAttributeMaxDynamicSharedMemorySize, SMTOT);

    presplit_x<<<2048, 256>>>(x);
    prep_weights<<<dim3(128, 2), 256>>>(w1, w2);
    prep_params<<<1, 128>>>(g1, b1, m1, v1, a1, g2, b2, m2, v2, a2, a3);

    dim3 grid(14, 7, 32);   // x: 7 w-tiles x 2 co-groups
    conv_mma<1><<<grid, 256, SMTOT>>>(nullptr, nullptr);
    conv_mma<2><<<grid, 256, SMTOT>>>(x, out);
}

// round 6
// speedup vs baseline: 3.7817x; 1.6069x over previous
#include <cuda_runtime.h>
#include <cuda_fp16.h>
#include <math.h>
#include <stdint.h>

#define CCH   128
#define HIMG  56
#define WIMG  56
#define NIMG  32
#define EPSBN 1e-5f
#define QLEV  255.0f
#define WMAXQ 127.0f

#define NPIX ((size_t)NIMG * CCH * HIMG * WIMG)

// ---------------- device scratch ----------------
// activations packed [n][ck8][h][w][ci16], hi/lo fp16 split
__device__ unsigned short g_xhi[NPIX],  g_xlo[NPIX];
__device__ unsigned short g_a1hi[NPIX], g_a1lo[NPIX];
// weights as INTEGER fp16 (exact): [ck8][rs9][co128][ci16]; per-co scale separate
#define WELEMS (8 * 9 * 128 * 16)
__device__ unsigned short g_w1i[WELEMS], g_w2i[WELEMS];
__device__ float g_ws1[CCH], g_ws2[CCH];
__device__ float g_bns1[CCH], g_bnb1[CCH], g_a1p[CCH], g_s1[CCH];
__device__ float g_bns2[CCH], g_bnb2[CCH], g_a2p[CCH], g_s2[CCH];
__device__ float g_a3p[CCH], g_s3[CCH];

// ---------------- PTX helpers (sm_80-class, valid for target sm_100) ------
__device__ __forceinline__ uint32_t smem_u32(const void* p) {
    uint32_t a;
    asm("{ .reg .u64 t; cvta.to.shared.u64 t, %1; cvt.u32.u64 %0, t; }" : "=r"(a) : "l"(p));
    return a;
}

__device__ __forceinline__ void cp16(uint32_t dst, const void* src, int sz) {
    asm volatile("cp.async.cg.shared.global [%0], [%1], 16, %2;"
                 :: "r"(dst), "l"(__cvta_generic_to_global(src)), "r"(sz) : "memory");
}
__device__ __forceinline__ void cp_commit() {
    asm volatile("cp.async.commit_group;" ::: "memory");
}
template <int N> __device__ __forceinline__ void cp_wait() {
    asm volatile("cp.async.wait_group %0;" :: "n"(N) : "memory");
}

__device__ __forceinline__ void ldsm4(uint32_t r[4], uint32_t addr) {
    asm volatile("ldmatrix.sync.aligned.m8n8.x4.shared.b16 {%0,%1,%2,%3}, [%4];"
                 : "=r"(r[0]), "=r"(r[1]), "=r"(r[2]), "=r"(r[3]) : "r"(addr));
}

__device__ __forceinline__ void mma16816(float d[4], const uint32_t a[4],
                                         uint32_t b0, uint32_t b1) {
    asm volatile("mma.sync.aligned.m16n8k16.row.col.f32.f16.f16.f32 "
                 "{%0,%1,%2,%3}, {%4,%5,%6,%7}, {%8,%9}, {%0,%1,%2,%3};"
                 : "+f"(d[0]), "+f"(d[1]), "+f"(d[2]), "+f"(d[3])
                 : "r"(a[0]), "r"(a[1]), "r"(a[2]), "r"(a[3]), "r"(b0), "r"(b1));
}

// ---------------- prep kernels ----------------
// coalesced split+pack: one thread per (n,ck,h,w) site, 2x 16B vector stores
__global__ void presplit_x(const float* __restrict__ x) {
    const size_t nsite = (size_t)NIMG * 8 * HIMG * WIMG;   // 802816
    size_t i = (size_t)blockIdx.x * blockDim.x + threadIdx.x;
    if (i >= nsite) return;
    int w  = (int)(i % 56);
    int h  = (int)((i / 56) % 56);
    int ck = (int)((i / 3136) % 8);
    int n  = (int)(i / 25088);
    unsigned short hi[16], lo[16];
#pragma unroll
    for (int j = 0; j < 16; j++) {
        float v = x[((size_t)(n * 128 + ck * 16 + j)) * 3136 + h * 56 + w];
        __half hh = __float2half_rn(v);
        __half ll = __float2half_rn((v - __half2float(hh)) * 2048.0f);
        hi[j] = __half_as_ushort(hh);
        lo[j] = __half_as_ushort(ll);
    }
    uint4* dh = (uint4*)(g_xhi + i * 16);
    uint4* dl = (uint4*)(g_xlo + i * 16);
    dh[0] = ((uint4*)hi)[0]; dh[1] = ((uint4*)hi)[1];
    dl[0] = ((uint4*)lo)[0]; dl[1] = ((uint4*)lo)[1];
}

__global__ void prep_weights(const float* __restrict__ w1, const float* __restrict__ w2) {
    const int o = blockIdx.x;
    const float* w = (blockIdx.y == 0) ? w1 : w2;
    unsigned short* di = (blockIdx.y == 0) ? g_w1i : g_w2i;
    float* ws          = (blockIdx.y == 0) ? g_ws1 : g_ws2;
    const float* wo = w + (size_t)o * CCH * 9;

    float m = 0.f;
    for (int i = threadIdx.x; i < CCH * 9; i += blockDim.x)
        m = fmaxf(m, fabsf(wo[i]));
    __shared__ float red[256];
    red[threadIdx.x] = m;
    __syncthreads();
    for (int s = 128; s > 0; s >>= 1) {
        if (threadIdx.x < s) red[threadIdx.x] = fmaxf(red[threadIdx.x], red[threadIdx.x + s]);
        __syncthreads();
    }
    const float scale = fmaxf(red[0] / WMAXQ, 1e-8f);
    if (threadIdx.x == 0) ws[o] = scale;

    for (int i = threadIdx.x; i < CCH * 9; i += blockDim.x) {
        int ci = i / 9, rs = i % 9;
        float k = fminf(fmaxf(rintf(wo[i] / scale), -WMAXQ), WMAXQ);  // integer, exact fp16
        size_t d = ((size_t)(((ci >> 4) * 9 + rs) * 128 + o) << 4) + (ci & 15);
        di[d] = __half_as_ushort(__float2half_rn(k));
    }
}

__global__ void prep_params(const float* g1, const float* b1, const float* m1, const float* v1,
                            const float* a1, const float* g2, const float* b2, const float* m2,
                            const float* v2, const float* a2, const float* a3) {
    const int c = threadIdx.x;
    if (c >= CCH) return;
    float sc1 = g1[c] / sqrtf(v1[c] + EPSBN);
    g_bns1[c] = sc1; g_bnb1[c] = b1[c] - m1[c] * sc1; g_a1p[c] = a1[c]; g_s1[c] = a1[c] / QLEV;
    float sc2 = g2[c] / sqrtf(v2[c] + EPSBN);
    g_bns2[c] = sc2; g_bnb2[c] = b2[c] - m2[c] * sc2; g_a2p[c] = a2[c]; g_s2[c] = a2[c] / QLEV;
    g_a3p[c] = a3[c]; g_s3[c] = a3[c] / QLEV;
}

// ---------------- smem layout per buffer ----------------
// [0,3200)       halo hi : 100 px * 32B ([h10][w10][ci16])
// [3200,6400)    halo lo
// [6400,24832)   int weights : [rs9][co64][ci16] fp16 = 18432B
#define WOFF   6400
#define BUFSZ  24832
#define SMTOT  (2 * BUFSZ)

// ---------------- fused conv stage (2-pass split-precision, int-B) --------
// CTA: 128 threads = 4 warps, each 32px x 32co; CTA covers 64px x 64co.
// 4 CTAs co-resident per SM.
template <int STAGE>
__global__ void __launch_bounds__(128, 4)
conv_mma(const float* __restrict__ x_res, float* __restrict__ out) {
    extern __shared__ char smem[];
    const uint32_t sb = smem_u32(smem);

    const int tid   = threadIdx.x;
    const int lane  = tid & 31;
    const int wid   = tid >> 5;
    const int warpM = wid & 1;      // 2 warps over M (32 px each)
    const int warpN = wid >> 1;     // 2 warps over N (32 co each)

    const int w0  = (blockIdx.x >> 1) * 8;
    const int co0 = (blockIdx.x & 1) * 64;
    const int h0  = blockIdx.y * 8;
    const int n   = blockIdx.z;

    const unsigned short* __restrict__ srcHi = (STAGE == 1) ? g_xhi : g_a1hi;
    const unsigned short* __restrict__ srcLo = (STAGE == 1) ? g_xlo : g_a1lo;
    const unsigned short* __restrict__ wInt  = (STAGE == 1) ? g_w1i : g_w2i;
    const float* __restrict__ wScl           = (STAGE == 1) ? g_ws1 : g_ws2;

    // ---- per-lane ldmatrix address components ----
    const int arow = lane & 15;
    const int akh  = (lane >> 4) * 16;
    const int bg   = lane >> 3;
    const int coL  = ((bg >> 1) << 3) + (lane & 7);
    const int bkh  = (bg & 1) * 16;
    uint32_t bAddrBase[2];
#pragma unroll
    for (int t = 0; t < 2; t++) {
        int co = warpN * 32 + t * 16 + coL;      // local co 0..63
        bAddrBase[t] = (uint32_t)WOFF + co * 32 + (uint32_t)(bkh ^ (((coL >> 2) & 1) * 16));
    }
    // A pixel rows for the two 16px m-tiles
    int phA[2], pwA[2];
#pragma unroll
    for (int m = 0; m < 2; m++) {
        int p = warpM * 32 + m * 16 + arow;
        phA[m] = p >> 3;
        pwA[m] = p & 7;
    }

    // ---- async-load helper ----
    auto issue_chunk = [&](int ck, int buf) {
        const uint32_t bufo = sb + buf * BUFSZ;
        // halo: 400 x 16B
        for (int e = tid; e < 400; e += 128) {
            int pix = e >> 2, split = (e >> 1) & 1, half = e & 1;
            int hh = pix / 10, ww = pix % 10;
            int hg = h0 - 1 + hh, wg = w0 - 1 + ww;
            bool inb = (hg >= 0) & (hg < HIMG) & (wg >= 0) & (wg < WIMG);
            size_t elem = inb ? (((((size_t)n * 8 + ck) * 56 + hg) * 56 + wg) * 16 + half * 8) : 0;
            const unsigned short* s = (split ? srcLo : srcHi) + elem;
            uint32_t d = bufo + split * 3200 +
                         (uint32_t)((pix * 32 + half * 16) ^ ((ww & 4) << 2));
            cp16(d, s, inb ? 16 : 0);
        }
        // int weights: 1152 x 16B
        for (int e2 = tid; e2 < 1152; e2 += 128) {
            int rs = e2 >> 7, u = e2 & 127;      // u = co_local*2 + half
            const unsigned short* s = wInt + (size_t)ck * 18432 + rs * 2048 + co0 * 16 + u * 8;
            uint32_t d = bufo + WOFF + (uint32_t)((e2 * 16) ^ ((e2 & 8) << 1));
            cp16(d, s, 16);
        }
        cp_commit();
    };

    float D0[2][4][4], D1[2][4][4];
#pragma unroll
    for (int m = 0; m < 2; m++)
#pragma unroll
        for (int f = 0; f < 4; f++)
#pragma unroll
            for (int j = 0; j < 4; j++) { D0[m][f][j] = 0.f; D1[m][f][j] = 0.f; }

    issue_chunk(0, 0);

    for (int ck = 0; ck < 8; ck++) {
        if (ck < 7) issue_chunk(ck + 1, (ck + 1) & 1);
        if (ck < 7) cp_wait<1>(); else cp_wait<0>();
        __syncthreads();

        const uint32_t sbuf = sb + (ck & 1) * BUFSZ;
#pragma unroll 3
        for (int rs = 0; rs < 9; rs++) {
            const int r = rs / 3, s = rs % 3;
            // A fragments (hi + lo) for both m-tiles
            uint32_t ah[2][4], al[2][4];
#pragma unroll
            for (int m = 0; m < 2; m++) {
                const int wcol = pwA[m] + s;
                uint32_t aaddr = sbuf + (uint32_t)(((phA[m] + r) * 10 + wcol) * 32) +
                                 (uint32_t)(akh ^ (((wcol >> 2) & 1) * 16));
                ldsm4(ah[m], aaddr);
                ldsm4(al[m], aaddr + 3200);
            }
            // B integer fragments (rs block stride = 64co*32B = 2048)
            const uint32_t bbase = sbuf + rs * 2048;
            uint32_t bi[2][4];
#pragma unroll
            for (int t = 0; t < 2; t++) ldsm4(bi[t], bbase + bAddrBase[t]);
            // 2-pass split-precision MMA (B exact)
#pragma unroll
            for (int m = 0; m < 2; m++)
#pragma unroll
                for (int t = 0; t < 2; t++)
#pragma unroll
                    for (int o = 0; o < 2; o++) {
                        const int nt = t * 2 + o;
                        mma16816(D0[m][nt], ah[m], bi[t][o * 2], bi[t][o * 2 + 1]);
                        mma16816(D1[m][nt], al[m], bi[t][o * 2], bi[t][o * 2 + 1]);
                    }
        }
        __syncthreads();
    }

    // ---------------- epilogue ----------------
    const int qrow = lane >> 2;
    const int rr   = lane & 3;
    const float inv2048 = 1.0f / 2048.0f;

#pragma unroll
    for (int m = 0; m < 2; m++)
#pragma unroll
        for (int nt = 0; nt < 4; nt++) {
            const int coB = co0 + warpN * 32 + nt * 8;
#pragma unroll
            for (int j = 0; j < 4; j++) {
                const int co = coB + 2 * rr + (j & 1);
                const int p  = warpM * 32 + m * 16 + qrow + (j >> 1) * 8;
                const int h  = h0 + (p >> 3);
                const int w  = w0 + (p & 7);
                float d = (D0[m][nt][j] + D1[m][nt][j] * inv2048) * wScl[co];
                if (STAGE == 1) {
                    float v  = d * g_bns1[co] + g_bnb1[co];
                    float cl = fminf(fmaxf(v, 0.f), g_a1p[co]);
                    float ss = g_s1[co];
                    float qv = rintf(cl / ss) * ss;
                    __half hq = __float2half_rn(qv);
                    __half lq = __float2half_rn((qv - __half2float(hq)) * 2048.0f);
                    size_t idx = ((((size_t)n * 8 + (co >> 4)) * 56 + h) * 56 + w) * 16 + (co & 15);
                    g_a1hi[idx] = __half_as_ushort(hq);
                    g_a1lo[idx] = __half_as_ushort(lq);
                } else {
                    float v  = d * g_bns2[co] + g_bnb2[co];
                    float cl = fminf(fmaxf(v, 0.f), g_a2p[co]);
                    float ss = g_s2[co];
                    float qv = rintf(cl / ss) * ss;
                    float s3 = g_s3[co];
                    size_t idx2 = (((size_t)n * 128 + co) * 56 + h) * 56 + w;
                    float y  = rintf(qv / s3) * s3 + rintf(x_res[idx2] / s3) * s3;
                    float yc = fminf(fmaxf(y, 0.f), g_a3p[co]);
                    out[idx2] = rintf(yc / s3) * s3;
                }
            }
        }
}

// ---------------- launch ----------------
extern "C" void kernel_launch(void* const* d_in, const int* in_sizes, int n_in,
                              void* d_out, int out_size) {
    const float* x  = (const float*)d_in[0];
    const float* w1 = (const float*)d_in[1];
    const float* g1 = (const float*)d_in[2];
    const float* b1 = (const float*)d_in[3];
    const float* m1 = (const float*)d_in[4];
    const float* v1 = (const float*)d_in[5];
    const float* a1 = (const float*)d_in[6];
    const float* w2 = (const float*)d_in[7];
    const float* g2 = (const float*)d_in[8];
    const float* b2 = (const float*)d_in[9];
    const float* m2 = (const float*)d_in[10];
    const float* v2 = (const float*)d_in[11];
    const float* a2 = (const float*)d_in[12];
    const float* a3 = (const float*)d_in[13];
    float* out = (float*)d_out;

    cudaFuncSetAttribute(conv_mma<1>, cudaFuncAttributeMaxDynamicSharedMemorySize, SMTOT);
    cudaFuncSetAttribute(conv_mma<2>, cudaFuncAttributeMaxDynamicSharedMemorySize, SMTOT);

    presplit_x<<<3136, 256>>>(x);
    prep_weights<<<dim3(128, 2), 256>>>(w1, w2);
    prep_params<<<1, 128>>>(g1, b1, m1, v1, a1, g2, b2, m2, v2, a2, a3);

    dim3 grid(14, 7, 32);   // x: 7 w-tiles x 2 co-groups
    conv_mma<1><<<grid, 128, SMTOT>>>(nullptr, nullptr);
    conv_mma<2><<<grid, 128, SMTOT>>>(x, out);
}

// round 7
// speedup vs baseline: 4.3075x; 1.1391x over previous
#include <cuda_runtime.h>
#include <cuda_fp16.h>
#include <math.h>
#include <stdint.h>

#define CCH   128
#define HIMG  56
#define WIMG  56
#define NIMG  32
#define EPSBN 1e-5f
#define QLEV  255.0f
#define WMAXQ 127.0f

#define NPIX ((size_t)NIMG * CCH * HIMG * WIMG)

// ---------------- device scratch ----------------
__device__ unsigned short g_xhi[NPIX],  g_xlo[NPIX];
__device__ unsigned short g_a1hi[NPIX], g_a1lo[NPIX];
#define WELEMS (8 * 9 * 128 * 16)
__device__ unsigned short g_w1i[WELEMS], g_w2i[WELEMS];
__device__ float g_ws1[CCH], g_ws2[CCH];
__device__ float g_bns1[CCH], g_bnb1[CCH], g_a1p[CCH], g_s1[CCH];
__device__ float g_bns2[CCH], g_bnb2[CCH], g_a2p[CCH], g_s2[CCH];
__device__ float g_a3p[CCH], g_s3[CCH];

// ---------------- PTX helpers (sm_80-class, valid for target sm_100) ------
__device__ __forceinline__ uint32_t smem_u32(const void* p) {
    uint32_t a;
    asm("{ .reg .u64 t; cvta.to.shared.u64 t, %1; cvt.u32.u64 %0, t; }" : "=r"(a) : "l"(p));
    return a;
}

__device__ __forceinline__ void cp16(uint32_t dst, const void* src, int sz) {
    asm volatile("cp.async.cg.shared.global [%0], [%1], 16, %2;"
                 :: "r"(dst), "l"(__cvta_generic_to_global(src)), "r"(sz) : "memory");
}
__device__ __forceinline__ void cp_commit() {
    asm volatile("cp.async.commit_group;" ::: "memory");
}
template <int N> __device__ __forceinline__ void cp_wait() {
    asm volatile("cp.async.wait_group %0;" :: "n"(N) : "memory");
}

__device__ __forceinline__ void ldsm4(uint32_t r[4], uint32_t addr) {
    asm volatile("ldmatrix.sync.aligned.m8n8.x4.shared.b16 {%0,%1,%2,%3}, [%4];"
                 : "=r"(r[0]), "=r"(r[1]), "=r"(r[2]), "=r"(r[3]) : "r"(addr));
}

__device__ __forceinline__ void mma16816(float d[4], const uint32_t a[4],
                                         uint32_t b0, uint32_t b1) {
    asm volatile("mma.sync.aligned.m16n8k16.row.col.f32.f16.f16.f32 "
                 "{%0,%1,%2,%3}, {%4,%5,%6,%7}, {%8,%9}, {%0,%1,%2,%3};"
                 : "+f"(d[0]), "+f"(d[1]), "+f"(d[2]), "+f"(d[3])
                 : "r"(a[0]), "r"(a[1]), "r"(a[2]), "r"(a[3]), "r"(b0), "r"(b1));
}

// ---------------- prep kernels ----------------
__global__ void presplit_x(const float* __restrict__ x) {
    const size_t nsite = (size_t)NIMG * 8 * HIMG * WIMG;
    size_t i = (size_t)blockIdx.x * blockDim.x + threadIdx.x;
    if (i >= nsite) return;
    int w  = (int)(i % 56);
    int h  = (int)((i / 56) % 56);
    int ck = (int)((i / 3136) % 8);
    int n  = (int)(i / 25088);
    unsigned short hi[16], lo[16];
#pragma unroll
    for (int j = 0; j < 16; j++) {
        float v = x[((size_t)(n * 128 + ck * 16 + j)) * 3136 + h * 56 + w];
        __half hh = __float2half_rn(v);
        __half ll = __float2half_rn((v - __half2float(hh)) * 2048.0f);
        hi[j] = __half_as_ushort(hh);
        lo[j] = __half_as_ushort(ll);
    }
    uint4* dh = (uint4*)(g_xhi + i * 16);
    uint4* dl = (uint4*)(g_xlo + i * 16);
    dh[0] = ((uint4*)hi)[0]; dh[1] = ((uint4*)hi)[1];
    dl[0] = ((uint4*)lo)[0]; dl[1] = ((uint4*)lo)[1];
}

__global__ void prep_weights(const float* __restrict__ w1, const float* __restrict__ w2) {
    const int o = blockIdx.x;
    const float* w = (blockIdx.y == 0) ? w1 : w2;
    unsigned short* di = (blockIdx.y == 0) ? g_w1i : g_w2i;
    float* ws          = (blockIdx.y == 0) ? g_ws1 : g_ws2;
    const float* wo = w + (size_t)o * CCH * 9;

    float m = 0.f;
    for (int i = threadIdx.x; i < CCH * 9; i += blockDim.x)
        m = fmaxf(m, fabsf(wo[i]));
    __shared__ float red[256];
    red[threadIdx.x] = m;
    __syncthreads();
    for (int s = 128; s > 0; s >>= 1) {
        if (threadIdx.x < s) red[threadIdx.x] = fmaxf(red[threadIdx.x], red[threadIdx.x + s]);
        __syncthreads();
    }
    const float scale = fmaxf(red[0] / WMAXQ, 1e-8f);
    if (threadIdx.x == 0) ws[o] = scale;

    for (int i = threadIdx.x; i < CCH * 9; i += blockDim.x) {
        int ci = i / 9, rs = i % 9;
        float k = fminf(fmaxf(rintf(wo[i] / scale), -WMAXQ), WMAXQ);
        size_t d = ((size_t)(((ci >> 4) * 9 + rs) * 128 + o) << 4) + (ci & 15);
        di[d] = __half_as_ushort(__float2half_rn(k));
    }
}

__global__ void prep_params(const float* g1, const float* b1, const float* m1, const float* v1,
                            const float* a1, const float* g2, const float* b2, const float* m2,
                            const float* v2, const float* a2, const float* a3) {
    const int c = threadIdx.x;
    if (c >= CCH) return;
    float sc1 = g1[c] / sqrtf(v1[c] + EPSBN);
    g_bns1[c] = sc1; g_bnb1[c] = b1[c] - m1[c] * sc1; g_a1p[c] = a1[c]; g_s1[c] = a1[c] / QLEV;
    float sc2 = g2[c] / sqrtf(v2[c] + EPSBN);
    g_bns2[c] = sc2; g_bnb2[c] = b2[c] - m2[c] * sc2; g_a2p[c] = a2[c]; g_s2[c] = a2[c] / QLEV;
    g_a3p[c] = a3[c]; g_s3[c] = a3[c] / QLEV;
}

// ---------------- smem layout per buffer ----------------
#define WOFF   6400
#define BUFSZ  24832
#define SMTOT  (2 * BUFSZ)

// ---------------- fused conv stage (2-pass split-precision, int-B) --------
template <int STAGE>
__global__ void __launch_bounds__(128, 4)
conv_mma(const float* __restrict__ x_res, float* __restrict__ out) {
    extern __shared__ char smem[];
    const uint32_t sb = smem_u32(smem);

    const int tid   = threadIdx.x;
    const int lane  = tid & 31;
    const int wid   = tid >> 5;
    const int warpM = wid & 1;
    const int warpN = wid >> 1;

    const int w0  = (blockIdx.x >> 1) * 8;
    const int co0 = (blockIdx.x & 1) * 64;
    const int h0  = blockIdx.y * 8;
    const int n   = blockIdx.z;

    const unsigned short* __restrict__ srcHi = (STAGE == 1) ? g_xhi : g_a1hi;
    const unsigned short* __restrict__ srcLo = (STAGE == 1) ? g_xlo : g_a1lo;
    const unsigned short* __restrict__ wInt  = (STAGE == 1) ? g_w1i : g_w2i;
    const float* __restrict__ wScl           = (STAGE == 1) ? g_ws1 : g_ws2;

    const int arow = lane & 15;
    const int akh  = (lane >> 4) * 16;
    const int bg   = lane >> 3;
    const int coL  = ((bg >> 1) << 3) + (lane & 7);
    const int bkh  = (bg & 1) * 16;
    uint32_t bAddrBase[2];
#pragma unroll
    for (int t = 0; t < 2; t++) {
        int co = warpN * 32 + t * 16 + coL;
        bAddrBase[t] = (uint32_t)WOFF + co * 32 + (uint32_t)(bkh ^ (((coL >> 2) & 1) * 16));
    }
    int phA[2], pwA[2];
#pragma unroll
    for (int m = 0; m < 2; m++) {
        int p = warpM * 32 + m * 16 + arow;
        phA[m] = p >> 3;
        pwA[m] = p & 7;
    }

    auto issue_chunk = [&](int ck, int buf) {
        const uint32_t bufo = sb + buf * BUFSZ;
        for (int e = tid; e < 400; e += 128) {
            int pix = e >> 2, split = (e >> 1) & 1, half = e & 1;
            int hh = pix / 10, ww = pix % 10;
            int hg = h0 - 1 + hh, wg = w0 - 1 + ww;
            bool inb = (hg >= 0) & (hg < HIMG) & (wg >= 0) & (wg < WIMG);
            size_t elem = inb ? (((((size_t)n * 8 + ck) * 56 + hg) * 56 + wg) * 16 + half * 8) : 0;
            const unsigned short* s = (split ? srcLo : srcHi) + elem;
            uint32_t d = bufo + split * 3200 +
                         (uint32_t)((pix * 32 + half * 16) ^ ((ww & 4) << 2));
            cp16(d, s, inb ? 16 : 0);
        }
        for (int e2 = tid; e2 < 1152; e2 += 128) {
            int rs = e2 >> 7, u = e2 & 127;
            const unsigned short* s = wInt + (size_t)ck * 18432 + rs * 2048 + co0 * 16 + u * 8;
            uint32_t d = bufo + WOFF + (uint32_t)((e2 * 16) ^ ((e2 & 8) << 1));
            cp16(d, s, 16);
        }
        cp_commit();
    };

    float D0[2][4][4], D1[2][4][4];
#pragma unroll
    for (int m = 0; m < 2; m++)
#pragma unroll
        for (int f = 0; f < 4; f++)
#pragma unroll
            for (int j = 0; j < 4; j++) { D0[m][f][j] = 0.f; D1[m][f][j] = 0.f; }

    issue_chunk(0, 0);

    for (int ck = 0; ck < 8; ck++) {
        if (ck < 7) issue_chunk(ck + 1, (ck + 1) & 1);
        if (ck < 7) cp_wait<1>(); else cp_wait<0>();
        __syncthreads();

        const uint32_t sbuf = sb + (ck & 1) * BUFSZ;
#pragma unroll 3
        for (int rs = 0; rs < 9; rs++) {
            const int r = rs / 3, s = rs % 3;
            uint32_t ah[2][4], al[2][4];
#pragma unroll
            for (int m = 0; m < 2; m++) {
                const int wcol = pwA[m] + s;
                uint32_t aaddr = sbuf + (uint32_t)(((phA[m] + r) * 10 + wcol) * 32) +
                                 (uint32_t)(akh ^ (((wcol >> 2) & 1) * 16));
                ldsm4(ah[m], aaddr);
                ldsm4(al[m], aaddr + 3200);
            }
            const uint32_t bbase = sbuf + rs * 2048;
            uint32_t bi[2][4];
#pragma unroll
            for (int t = 0; t < 2; t++) ldsm4(bi[t], bbase + bAddrBase[t]);
#pragma unroll
            for (int m = 0; m < 2; m++)
#pragma unroll
                for (int t = 0; t < 2; t++)
#pragma unroll
                    for (int o = 0; o < 2; o++) {
                        const int nt = t * 2 + o;
                        mma16816(D0[m][nt], ah[m], bi[t][o * 2], bi[t][o * 2 + 1]);
                        mma16816(D1[m][nt], al[m], bi[t][o * 2], bi[t][o * 2 + 1]);
                    }
        }
        __syncthreads();
    }

    // ---------------- epilogue: BN+PACT into smem, then coalesced writers --
    float* qs = (float*)smem;           // [64 px][65] fp32 tile (mainloop smem dead)
    const int qrow = lane >> 2;
    const int rr   = lane & 3;
    const float inv2048 = 1.0f / 2048.0f;

#pragma unroll
    for (int m = 0; m < 2; m++)
#pragma unroll
        for (int nt = 0; nt < 4; nt++) {
            const int col = warpN * 32 + nt * 8;       // local co base
#pragma unroll
            for (int j = 0; j < 4; j++) {
                const int cl_ = col + 2 * rr + (j & 1);  // local co 0..63
                const int co  = co0 + cl_;
                const int p   = warpM * 32 + m * 16 + qrow + (j >> 1) * 8;  // local px
                float d = (D0[m][nt][j] + D1[m][nt][j] * inv2048) * wScl[co];
                float v, aa, ss;
                if (STAGE == 1) { v = d * g_bns1[co] + g_bnb1[co]; aa = g_a1p[co]; ss = g_s1[co]; }
                else            { v = d * g_bns2[co] + g_bnb2[co]; aa = g_a2p[co]; ss = g_s2[co]; }
                float cl2 = fminf(fmaxf(v, 0.f), aa);
                qs[p * 65 + cl_] = rintf(cl2 / ss) * ss;   // PACT fake-quant value
            }
        }
    __syncthreads();

    if (STAGE == 1) {
        // writers: thread = (split, px); 4x 32B contiguous stores per thread
        const int split = tid >> 6;
        const int px    = tid & 63;
        const int h = h0 + (px >> 3), w = w0 + (px & 7);
#pragma unroll
        for (int g = 0; g < 4; g++) {
            unsigned short vals[16];
#pragma unroll
            for (int c = 0; c < 16; c++) {
                float q = qs[px * 65 + g * 16 + c];
                __half hh = __float2half_rn(q);
                if (split == 0) vals[c] = __half_as_ushort(hh);
                else vals[c] = __half_as_ushort(
                         __float2half_rn((q - __half2float(hh)) * 2048.0f));
            }
            const int ck = (co0 >> 4) + g;
            size_t site = (((size_t)n * 8 + ck) * 56 + h) * 56 + w;
            unsigned short* dst = (split ? g_a1lo : g_a1hi) + site * 16;
            ((uint4*)dst)[0] = ((uint4*)vals)[0];
            ((uint4*)dst)[1] = ((uint4*)vals)[1];
        }
    } else {
        // writers: 512 (co,h) rows; 8 w-consecutive floats each (float4 x2)
#pragma unroll
        for (int k = 0; k < 4; k++) {
            const int q  = tid + 128 * k;
            const int cl_ = q >> 3;            // local co 0..63
            const int hl  = q & 7;
            const int co  = co0 + cl_;
            const int h   = h0 + hl;
            const float s3  = g_s3[co];
            const float a3v = g_a3p[co];
            const size_t base = (((size_t)n * 128 + co) * 56 + h) * 56 + w0;
            float4 x0 = *(const float4*)(x_res + base);
            float4 x1 = *(const float4*)(x_res + base + 4);
            float xv[8] = {x0.x, x0.y, x0.z, x0.w, x1.x, x1.y, x1.z, x1.w};
            float ov[8];
#pragma unroll
            for (int w = 0; w < 8; w++) {
                float qv = qs[(hl * 8 + w) * 65 + cl_];
                float y  = rintf(qv / s3) * s3 + rintf(xv[w] / s3) * s3;
                float yc = fminf(fmaxf(y, 0.f), a3v);
                ov[w] = rintf(yc / s3) * s3;
            }
            *(float4*)(out + base)     = make_float4(ov[0], ov[1], ov[2], ov[3]);
            *(float4*)(out + base + 4) = make_float4(ov[4], ov[5], ov[6], ov[7]);
        }
    }
}

// ---------------- launch ----------------
extern "C" void kernel_launch(void* const* d_in, const int* in_sizes, int n_in,
                              void* d_out, int out_size) {
    const float* x  = (const float*)d_in[0];
    const float* w1 = (const float*)d_in[1];
    const float* g1 = (const float*)d_in[2];
    const float* b1 = (const float*)d_in[3];
    const float* m1 = (const float*)d_in[4];
    const float* v1 = (const float*)d_in[5];
    const float* a1 = (const float*)d_in[6];
    const float* w2 = (const float*)d_in[7];
    const float* g2 = (const float*)d_in[8];
    const float* b2 = (const float*)d_in[9];
    const float* m2 = (const float*)d_in[10];
    const float* v2 = (const float*)d_in[11];
    const float* a2 = (const float*)d_in[12];
    const float* a3 = (const float*)d_in[13];
    float* out = (float*)d_out;

    cudaFuncSetAttribute(conv_mma<1>, cudaFuncAttributeMaxDynamicSharedMemorySize, SMTOT);
    cudaFuncSetAttribute(conv_mma<2>, cudaFuncAttributeMaxDynamicSharedMemorySize, SMTOT);

    presplit_x<<<3136, 256>>>(x);
    prep_weights<<<dim3(128, 2), 256>>>(w1, w2);
    prep_params<<<1, 128>>>(g1, b1, m1, v1, a1, g2, b2, m2, v2, a2, a3);

    dim3 grid(14, 7, 32);
    conv_mma<1><<<grid, 128, SMTOT>>>(nullptr, nullptr);
    conv_mma<2><<<grid, 128, SMTOT>>>(x, out);
}

// round 8
// speedup vs baseline: 5.5663x; 1.2922x over previous
#include <cuda_runtime.h>
#include <cuda_fp16.h>
#include <math.h>
#include <stdint.h>

#define CCH   128
#define HIMG  56
#define WIMG  56
#define NIMG  32
#define EPSBN 1e-5f
#define QLEV  255.0f
#define WMAXQ 127.0f

#define NPIX ((size_t)NIMG * CCH * HIMG * WIMG)

// ---------------- device scratch ----------------
__device__ unsigned short g_xhi[NPIX],  g_xlo[NPIX];
__device__ unsigned short g_a1hi[NPIX], g_a1lo[NPIX];
#define WELEMS (8 * 9 * 128 * 16)
__device__ unsigned short g_w1i[WELEMS], g_w2i[WELEMS];
__device__ float g_ws1[CCH], g_ws2[CCH];
__device__ float g_bns1[CCH], g_bnb1[CCH], g_a1p[CCH], g_s1[CCH], g_r1[CCH];
__device__ float g_bns2[CCH], g_bnb2[CCH], g_a2p[CCH], g_s2[CCH], g_r2[CCH];
__device__ float g_a3p[CCH], g_s3[CCH], g_r3[CCH];

// ---------------- PTX helpers (sm_80-class, valid for target sm_100) ------
__device__ __forceinline__ uint32_t smem_u32(const void* p) {
    uint32_t a;
    asm("{ .reg .u64 t; cvta.to.shared.u64 t, %1; cvt.u32.u64 %0, t; }" : "=r"(a) : "l"(p));
    return a;
}

__device__ __forceinline__ void cp16(uint32_t dst, const void* src, int sz) {
    asm volatile("cp.async.cg.shared.global [%0], [%1], 16, %2;"
                 :: "r"(dst), "l"(__cvta_generic_to_global(src)), "r"(sz) : "memory");
}
__device__ __forceinline__ void cp_commit() {
    asm volatile("cp.async.commit_group;" ::: "memory");
}
template <int N> __device__ __forceinline__ void cp_wait() {
    asm volatile("cp.async.wait_group %0;" :: "n"(N) : "memory");
}

__device__ __forceinline__ void ldsm4(uint32_t r[4], uint32_t addr) {
    asm volatile("ldmatrix.sync.aligned.m8n8.x4.shared.b16 {%0,%1,%2,%3}, [%4];"
                 : "=r"(r[0]), "=r"(r[1]), "=r"(r[2]), "=r"(r[3]) : "r"(addr));
}

__device__ __forceinline__ void mma16816(float d[4], const uint32_t a[4],
                                         uint32_t b0, uint32_t b1) {
    asm volatile("mma.sync.aligned.m16n8k16.row.col.f32.f16.f16.f32 "
                 "{%0,%1,%2,%3}, {%4,%5,%6,%7}, {%8,%9}, {%0,%1,%2,%3};"
                 : "+f"(d[0]), "+f"(d[1]), "+f"(d[2]), "+f"(d[3])
                 : "r"(a[0]), "r"(a[1]), "r"(a[2]), "r"(a[3]), "r"(b0), "r"(b1));
}

// exact exponent shift: x * 2^-11 on packed half2 (k integer => stays normal)
__device__ __forceinline__ uint32_t hscale11(uint32_t b) {
    const __half2 s = __floats2half2_rn(4.8828125e-4f, 4.8828125e-4f);  // 2^-11
    __half2 v = *reinterpret_cast<__half2*>(&b);
    v = __hmul2(v, s);
    return *reinterpret_cast<uint32_t*>(&v);
}

// ---------------- prep kernels ----------------
__global__ void presplit_x(const float* __restrict__ x) {
    const size_t nsite = (size_t)NIMG * 8 * HIMG * WIMG;
    size_t i = (size_t)blockIdx.x * blockDim.x + threadIdx.x;
    if (i >= nsite) return;
    int w  = (int)(i % 56);
    int h  = (int)((i / 56) % 56);
    int ck = (int)((i / 3136) % 8);
    int n  = (int)(i / 25088);
    unsigned short hi[16], lo[16];
#pragma unroll
    for (int j = 0; j < 16; j++) {
        float v = x[((size_t)(n * 128 + ck * 16 + j)) * 3136 + h * 56 + w];
        __half hh = __float2half_rn(v);
        __half ll = __float2half_rn((v - __half2float(hh)) * 2048.0f);
        hi[j] = __half_as_ushort(hh);
        lo[j] = __half_as_ushort(ll);
    }
    uint4* dh = (uint4*)(g_xhi + i * 16);
    uint4* dl = (uint4*)(g_xlo + i * 16);
    dh[0] = ((uint4*)hi)[0]; dh[1] = ((uint4*)hi)[1];
    dl[0] = ((uint4*)lo)[0]; dl[1] = ((uint4*)lo)[1];
}

__global__ void prep_weights(const float* __restrict__ w1, const float* __restrict__ w2) {
    const int o = blockIdx.x;
    const float* w = (blockIdx.y == 0) ? w1 : w2;
    unsigned short* di = (blockIdx.y == 0) ? g_w1i : g_w2i;
    float* ws          = (blockIdx.y == 0) ? g_ws1 : g_ws2;
    const float* wo = w + (size_t)o * CCH * 9;

    float m = 0.f;
    for (int i = threadIdx.x; i < CCH * 9; i += blockDim.x)
        m = fmaxf(m, fabsf(wo[i]));
    __shared__ float red[256];
    red[threadIdx.x] = m;
    __syncthreads();
    for (int s = 128; s > 0; s >>= 1) {
        if (threadIdx.x < s) red[threadIdx.x] = fmaxf(red[threadIdx.x], red[threadIdx.x + s]);
        __syncthreads();
    }
    const float scale = fmaxf(red[0] / WMAXQ, 1e-8f);
    if (threadIdx.x == 0) ws[o] = scale;

    for (int i = threadIdx.x; i < CCH * 9; i += blockDim.x) {
        int ci = i / 9, rs = i % 9;
        float k = fminf(fmaxf(rintf(wo[i] / scale), -WMAXQ), WMAXQ);
        size_t d = ((size_t)(((ci >> 4) * 9 + rs) * 128 + o) << 4) + (ci & 15);
        di[d] = __half_as_ushort(__float2half_rn(k));
    }
}

__global__ void prep_params(const float* g1, const float* b1, const float* m1, const float* v1,
                            const float* a1, const float* g2, const float* b2, const float* m2,
                            const float* v2, const float* a2, const float* a3) {
    const int c = threadIdx.x;
    if (c >= CCH) return;
    float sc1 = g1[c] / sqrtf(v1[c] + EPSBN);
    g_bns1[c] = sc1; g_bnb1[c] = b1[c] - m1[c] * sc1; g_a1p[c] = a1[c];
    g_s1[c] = a1[c] / QLEV; g_r1[c] = 1.0f / g_s1[c];
    float sc2 = g2[c] / sqrtf(v2[c] + EPSBN);
    g_bns2[c] = sc2; g_bnb2[c] = b2[c] - m2[c] * sc2; g_a2p[c] = a2[c];
    g_s2[c] = a2[c] / QLEV; g_r2[c] = 1.0f / g_s2[c];
    g_a3p[c] = a3[c]; g_s3[c] = a3[c] / QLEV; g_r3[c] = 1.0f / g_s3[c];
}

// ---------------- smem layout per buffer ----------------
#define WOFF   6400
#define BUFSZ  24832
#define SMTOT  (2 * BUFSZ)

// ---------------- fused conv stage (K-packed split-precision, int-B) ------
template <int STAGE>
__global__ void __launch_bounds__(128, 4)
conv_mma(const float* __restrict__ x_res, float* __restrict__ out) {
    extern __shared__ char smem[];
    const uint32_t sb = smem_u32(smem);

    const int tid   = threadIdx.x;
    const int lane  = tid & 31;
    const int wid   = tid >> 5;
    const int warpM = wid & 1;
    const int warpN = wid >> 1;

    const int w0  = (blockIdx.x >> 1) * 8;
    const int co0 = (blockIdx.x & 1) * 64;
    const int h0  = blockIdx.y * 8;
    const int n   = blockIdx.z;

    const unsigned short* __restrict__ srcHi = (STAGE == 1) ? g_xhi : g_a1hi;
    const unsigned short* __restrict__ srcLo = (STAGE == 1) ? g_xlo : g_a1lo;
    const unsigned short* __restrict__ wInt  = (STAGE == 1) ? g_w1i : g_w2i;
    const float* __restrict__ wScl           = (STAGE == 1) ? g_ws1 : g_ws2;

    const int arow = lane & 15;
    const int akh  = (lane >> 4) * 16;
    const int bg   = lane >> 3;
    const int coL  = ((bg >> 1) << 3) + (lane & 7);
    const int bkh  = (bg & 1) * 16;
    uint32_t bAddrBase[2];
#pragma unroll
    for (int t = 0; t < 2; t++) {
        int co = warpN * 32 + t * 16 + coL;
        bAddrBase[t] = (uint32_t)WOFF + co * 32 + (uint32_t)(bkh ^ (((coL >> 2) & 1) * 16));
    }
    int phA[2], pwA[2];
#pragma unroll
    for (int m = 0; m < 2; m++) {
        int p = warpM * 32 + m * 16 + arow;
        phA[m] = p >> 3;
        pwA[m] = p & 7;
    }

    auto issue_chunk = [&](int ck, int buf) {
        const uint32_t bufo = sb + buf * BUFSZ;
        for (int e = tid; e < 400; e += 128) {
            int pix = e >> 2, split = (e >> 1) & 1, half = e & 1;
            int hh = pix / 10, ww = pix % 10;
            int hg = h0 - 1 + hh, wg = w0 - 1 + ww;
            bool inb = (hg >= 0) & (hg < HIMG) & (wg >= 0) & (wg < WIMG);
            size_t elem = inb ? (((((size_t)n * 8 + ck) * 56 + hg) * 56 + wg) * 16 + half * 8) : 0;
            const unsigned short* s = (split ? srcLo : srcHi) + elem;
            uint32_t d = bufo + split * 3200 +
                         (uint32_t)((pix * 32 + half * 16) ^ ((ww & 4) << 2));
            cp16(d, s, inb ? 16 : 0);
        }
        for (int e2 = tid; e2 < 1152; e2 += 128) {
            int rs = e2 >> 7, u = e2 & 127;
            const unsigned short* s = wInt + (size_t)ck * 18432 + rs * 2048 + co0 * 16 + u * 8;
            uint32_t d = bufo + WOFF + (uint32_t)((e2 * 16) ^ ((e2 & 8) << 1));
            cp16(d, s, 16);
        }
        cp_commit();
    };

    // single accumulator set (K-packed split precision)
    float D[2][4][4];
#pragma unroll
    for (int m = 0; m < 2; m++)
#pragma unroll
        for (int f = 0; f < 4; f++)
#pragma unroll
            for (int j = 0; j < 4; j++) D[m][f][j] = 0.f;

    issue_chunk(0, 0);

    for (int ck = 0; ck < 8; ck++) {
        if (ck < 7) issue_chunk(ck + 1, (ck + 1) & 1);
        if (ck < 7) cp_wait<1>(); else cp_wait<0>();
        __syncthreads();

        const uint32_t sbuf = sb + (ck & 1) * BUFSZ;
#pragma unroll
        for (int rs = 0; rs < 9; rs++) {
            const int r = rs / 3, s = rs % 3;
            uint32_t ah[2][4], al[2][4];
#pragma unroll
            for (int m = 0; m < 2; m++) {
                const int wcol = pwA[m] + s;
                uint32_t aaddr = sbuf + (uint32_t)(((phA[m] + r) * 10 + wcol) * 32) +
                                 (uint32_t)(akh ^ (((wcol >> 2) & 1) * 16));
                ldsm4(ah[m], aaddr);
                ldsm4(al[m], aaddr + 3200);
            }
            const uint32_t bbase = sbuf + rs * 2048;
            uint32_t bi[2][4], bs[2][4];
#pragma unroll
            for (int t = 0; t < 2; t++) {
                ldsm4(bi[t], bbase + bAddrBase[t]);
#pragma unroll
                for (int q = 0; q < 4; q++) bs[t][q] = hscale11(bi[t][q]);
            }
#pragma unroll
            for (int m = 0; m < 2; m++)
#pragma unroll
                for (int t = 0; t < 2; t++)
#pragma unroll
                    for (int o = 0; o < 2; o++) {
                        const int nt = t * 2 + o;
                        mma16816(D[m][nt], ah[m], bi[t][o * 2], bi[t][o * 2 + 1]);
                        mma16816(D[m][nt], al[m], bs[t][o * 2], bs[t][o * 2 + 1]);
                    }
        }
        __syncthreads();
    }

    // ---------------- epilogue: BN+PACT into smem, then coalesced writers --
    float* qs = (float*)smem;           // [64 px][65] fp32
    const int qrow = lane >> 2;
    const int rr   = lane & 3;

#pragma unroll
    for (int m = 0; m < 2; m++)
#pragma unroll
        for (int nt = 0; nt < 4; nt++) {
            const int col = warpN * 32 + nt * 8;
#pragma unroll
            for (int j = 0; j < 4; j++) {
                const int cl_ = col + 2 * rr + (j & 1);
                const int co  = co0 + cl_;
                const int p   = warpM * 32 + m * 16 + qrow + (j >> 1) * 8;
                float d = D[m][nt][j] * wScl[co];
                float v, aa, ss, rr2;
                if (STAGE == 1) { v = d * g_bns1[co] + g_bnb1[co]; aa = g_a1p[co]; ss = g_s1[co]; rr2 = g_r1[co]; }
                else            { v = d * g_bns2[co] + g_bnb2[co]; aa = g_a2p[co]; ss = g_s2[co]; rr2 = g_r2[co]; }
                float cl2 = fminf(fmaxf(v, 0.f), aa);
                qs[p * 65 + cl_] = rintf(cl2 * rr2) * ss;
            }
        }
    __syncthreads();

    if (STAGE == 1) {
        const int split = tid >> 6;
        const int px    = tid & 63;
        const int h = h0 + (px >> 3), w = w0 + (px & 7);
#pragma unroll
        for (int g = 0; g < 4; g++) {
            unsigned short vals[16];
#pragma unroll
            for (int c = 0; c < 16; c++) {
                float q = qs[px * 65 + g * 16 + c];
                __half hh = __float2half_rn(q);
                if (split == 0) vals[c] = __half_as_ushort(hh);
                else vals[c] = __half_as_ushort(
                         __float2half_rn((q - __half2float(hh)) * 2048.0f));
            }
            const int ck = (co0 >> 4) + g;
            size_t site = (((size_t)n * 8 + ck) * 56 + h) * 56 + w;
            unsigned short* dst = (split ? g_a1lo : g_a1hi) + site * 16;
            ((uint4*)dst)[0] = ((uint4*)vals)[0];
            ((uint4*)dst)[1] = ((uint4*)vals)[1];
        }
    } else {
#pragma unroll
        for (int k = 0; k < 4; k++) {
            const int q   = tid + 128 * k;
            const int cl_ = q >> 3;
            const int hl  = q & 7;
            const int co  = co0 + cl_;
            const int h   = h0 + hl;
            const float s3  = g_s3[co];
            const float r3  = g_r3[co];
            const float a3v = g_a3p[co];
            const size_t base = (((size_t)n * 128 + co) * 56 + h) * 56 + w0;
            float4 x0 = *(const float4*)(x_res + base);
            float4 x1 = *(const float4*)(x_res + base + 4);
            float xv[8] = {x0.x, x0.y, x0.z, x0.w, x1.x, x1.y, x1.z, x1.w};
            float ov[8];
#pragma unroll
            for (int w = 0; w < 8; w++) {
                float qv = qs[(hl * 8 + w) * 65 + cl_];
                float y  = rintf(qv * r3) * s3 + rintf(xv[w] * r3) * s3;
                float yc = fminf(fmaxf(y, 0.f), a3v);
                ov[w] = rintf(yc * r3) * s3;
            }
            *(float4*)(out + base)     = make_float4(ov[0], ov[1], ov[2], ov[3]);
            *(float4*)(out + base + 4) = make_float4(ov[4], ov[5], ov[6], ov[7]);
        }
    }
}

// ---------------- launch ----------------
extern "C" void kernel_launch(void* const* d_in, const int* in_sizes, int n_in,
                              void* d_out, int out_size) {
    const float* x  = (const float*)d_in[0];
    const float* w1 = (const float*)d_in[1];
    const float* g1 = (const float*)d_in[2];
    const float* b1 = (const float*)d_in[3];
    const float* m1 = (const float*)d_in[4];
    const float* v1 = (const float*)d_in[5];
    const float* a1 = (const float*)d_in[6];
    const float* w2 = (const float*)d_in[7];
    const float* g2 = (const float*)d_in[8];
    const float* b2 = (const float*)d_in[9];
    const float* m2 = (const float*)d_in[10];
    const float* v2 = (const float*)d_in[11];
    const float* a2 = (const float*)d_in[12];
    const float* a3 = (const float*)d_in[13];
    float* out = (float*)d_out;

    cudaFuncSetAttribute(conv_mma<1>, cudaFuncAttributeMaxDynamicSharedMemorySize, SMTOT);
    cudaFuncSetAttribute(conv_mma<2>, cudaFuncAttributeMaxDynamicSharedMemorySize, SMTOT);

    presplit_x<<<3136, 256>>>(x);
    prep_weights<<<dim3(128, 2), 256>>>(w1, w2);
    prep_params<<<1, 128>>>(g1, b1, m1, v1, a1, g2, b2, m2, v2, a2, a3);

    dim3 grid(14, 7, 32);
    conv_mma<1><<<grid, 128, SMTOT>>>(nullptr, nullptr);
    conv_mma<2><<<grid, 128, SMTOT>>>(x, out);
}

// round 9
// speedup vs baseline: 5.8266x; 1.0468x over previous
#include <cuda_runtime.h>
#include <cuda_fp16.h>
#include <math.h>
#include <stdint.h>

#define CCH   128
#define HIMG  56
#define WIMG  56
#define NIMG  32
#define EPSBN 1e-5f
#define QLEV  255.0f
#define WMAXQ 127.0f

#define NPIX ((size_t)NIMG * CCH * HIMG * WIMG)

// ---------------- device scratch ----------------
__device__ unsigned short g_xhi[NPIX],  g_xlo[NPIX];
__device__ unsigned short g_a1hi[NPIX], g_a1lo[NPIX];
#define WELEMS (8 * 9 * 128 * 16)
__device__ unsigned short g_w1i[WELEMS], g_w2i[WELEMS];
__device__ float g_ws1[CCH], g_ws2[CCH];
__device__ float g_bns1[CCH], g_bnb1[CCH], g_a1p[CCH], g_s1[CCH], g_r1[CCH];
__device__ float g_bns2[CCH], g_bnb2[CCH], g_a2p[CCH], g_s2[CCH], g_r2[CCH];
__device__ float g_a3p[CCH], g_s3[CCH], g_r3[CCH];

// ---------------- PTX helpers ----------------
__device__ __forceinline__ uint32_t smem_u32(const void* p) {
    uint32_t a;
    asm("{ .reg .u64 t; cvta.to.shared.u64 t, %1; cvt.u32.u64 %0, t; }" : "=r"(a) : "l"(p));
    return a;
}

__device__ __forceinline__ void cp16(uint32_t dst, const void* src, int sz) {
    asm volatile("cp.async.cg.shared.global [%0], [%1], 16, %2;"
                 :: "r"(dst), "l"(__cvta_generic_to_global(src)), "r"(sz) : "memory");
}
__device__ __forceinline__ void cp_commit() {
    asm volatile("cp.async.commit_group;" ::: "memory");
}
template <int N> __device__ __forceinline__ void cp_wait() {
    asm volatile("cp.async.wait_group %0;" :: "n"(N) : "memory");
}

__device__ __forceinline__ void ldsm4(uint32_t r[4], uint32_t addr) {
    asm volatile("ldmatrix.sync.aligned.m8n8.x4.shared.b16 {%0,%1,%2,%3}, [%4];"
                 : "=r"(r[0]), "=r"(r[1]), "=r"(r[2]), "=r"(r[3]) : "r"(addr));
}

__device__ __forceinline__ void mma16816(float d[4], const uint32_t a[4],
                                         uint32_t b0, uint32_t b1) {
    asm volatile("mma.sync.aligned.m16n8k16.row.col.f32.f16.f16.f32 "
                 "{%0,%1,%2,%3}, {%4,%5,%6,%7}, {%8,%9}, {%0,%1,%2,%3};"
                 : "+f"(d[0]), "+f"(d[1]), "+f"(d[2]), "+f"(d[3])
                 : "r"(a[0]), "r"(a[1]), "r"(a[2]), "r"(a[3]), "r"(b0), "r"(b1));
}

// exact exponent shift: x * 2^-11 on packed half2 (k integer => stays normal)
__device__ __forceinline__ uint32_t hscale11(uint32_t b) {
    const __half2 s = __floats2half2_rn(4.8828125e-4f, 4.8828125e-4f);
    __half2 v = *reinterpret_cast<__half2*>(&b);
    v = __hmul2(v, s);
    return *reinterpret_cast<uint32_t*>(&v);
}

// ---------------- prep kernels ----------------
__global__ void presplit_x(const float* __restrict__ x) {
    const size_t nsite = (size_t)NIMG * 8 * HIMG * WIMG;
    size_t i = (size_t)blockIdx.x * blockDim.x + threadIdx.x;
    if (i >= nsite) return;
    int w  = (int)(i % 56);
    int h  = (int)((i / 56) % 56);
    int ck = (int)((i / 3136) % 8);
    int n  = (int)(i / 25088);
    unsigned short hi[16], lo[16];
#pragma unroll
    for (int j = 0; j < 16; j++) {
        float v = x[((size_t)(n * 128 + ck * 16 + j)) * 3136 + h * 56 + w];
        __half hh = __float2half_rn(v);
        __half ll = __float2half_rn((v - __half2float(hh)) * 2048.0f);
        hi[j] = __half_as_ushort(hh);
        lo[j] = __half_as_ushort(ll);
    }
    uint4* dh = (uint4*)(g_xhi + i * 16);
    uint4* dl = (uint4*)(g_xlo + i * 16);
    dh[0] = ((uint4*)hi)[0]; dh[1] = ((uint4*)hi)[1];
    dl[0] = ((uint4*)lo)[0]; dl[1] = ((uint4*)lo)[1];
}

__global__ void prep_weights(const float* __restrict__ w1, const float* __restrict__ w2) {
    const int o = blockIdx.x;
    const float* w = (blockIdx.y == 0) ? w1 : w2;
    unsigned short* di = (blockIdx.y == 0) ? g_w1i : g_w2i;
    float* ws          = (blockIdx.y == 0) ? g_ws1 : g_ws2;
    const float* wo = w + (size_t)o * CCH * 9;

    float m = 0.f;
    for (int i = threadIdx.x; i < CCH * 9; i += blockDim.x)
        m = fmaxf(m, fabsf(wo[i]));
    __shared__ float red[256];
    red[threadIdx.x] = m;
    __syncthreads();
    for (int s = 128; s > 0; s >>= 1) {
        if (threadIdx.x < s) red[threadIdx.x] = fmaxf(red[threadIdx.x], red[threadIdx.x + s]);
        __syncthreads();
    }
    const float scale = fmaxf(red[0] / WMAXQ, 1e-8f);
    if (threadIdx.x == 0) ws[o] = scale;

    for (int i = threadIdx.x; i < CCH * 9; i += blockDim.x) {
        int ci = i / 9, rs = i % 9;
        float k = fminf(fmaxf(rintf(wo[i] / scale), -WMAXQ), WMAXQ);
        size_t d = ((size_t)(((ci >> 4) * 9 + rs) * 128 + o) << 4) + (ci & 15);
        di[d] = __half_as_ushort(__float2half_rn(k));
    }
}

__global__ void prep_params(const float* g1, const float* b1, const float* m1, const float* v1,
                            const float* a1, const float* g2, const float* b2, const float* m2,
                            const float* v2, const float* a2, const float* a3) {
    const int c = threadIdx.x;
    if (c >= CCH) return;
    float sc1 = g1[c] / sqrtf(v1[c] + EPSBN);
    g_bns1[c] = sc1; g_bnb1[c] = b1[c] - m1[c] * sc1; g_a1p[c] = a1[c];
    g_s1[c] = a1[c] / QLEV; g_r1[c] = 1.0f / g_s1[c];
    float sc2 = g2[c] / sqrtf(v2[c] + EPSBN);
    g_bns2[c] = sc2; g_bnb2[c] = b2[c] - m2[c] * sc2; g_a2p[c] = a2[c];
    g_s2[c] = a2[c] / QLEV; g_r2[c] = 1.0f / g_s2[c];
    g_a3p[c] = a3[c]; g_s3[c] = a3[c] / QLEV; g_r3[c] = 1.0f / g_s3[c];
}

// ---------------- smem layout per buffer ----------------
// [0,3200)       halo hi ; [3200,6400) halo lo
// [6400,43264)   int weights [rs9][co128][ci16] = 36864B
#define WOFF   6400
#define BUFSZ  43264
#define SMTOT  (2 * BUFSZ)

// ---------------- fused conv stage: CTA 64px x 128co, warp 32px x 64co ----
template <int STAGE>
__global__ void __launch_bounds__(128, 2)
conv_mma(const float* __restrict__ x_res, float* __restrict__ out) {
    extern __shared__ char smem[];
    const uint32_t sb = smem_u32(smem);

    const int tid   = threadIdx.x;
    const int lane  = tid & 31;
    const int wid   = tid >> 5;
    const int warpM = wid & 1;      // 2 warps over M (32 px each)
    const int warpN = wid >> 1;     // 2 warps over N (64 co each)

    const int w0 = blockIdx.x * 8;
    const int h0 = blockIdx.y * 8;
    const int n  = blockIdx.z;

    const unsigned short* __restrict__ srcHi = (STAGE == 1) ? g_xhi : g_a1hi;
    const unsigned short* __restrict__ srcLo = (STAGE == 1) ? g_xlo : g_a1lo;
    const unsigned short* __restrict__ wInt  = (STAGE == 1) ? g_w1i : g_w2i;
    const float* __restrict__ wScl           = (STAGE == 1) ? g_ws1 : g_ws2;

    // ---- ldmatrix lane addressing ----
    const int arow = lane & 15;
    const int akh  = (lane >> 4) * 16;
    const int bg   = lane >> 3;
    const int coL  = ((bg >> 1) << 3) + (lane & 7);
    const int bkh  = (bg & 1) * 16;
    uint32_t bAddrBase[4];
#pragma unroll
    for (int t = 0; t < 4; t++) {
        int co = warpN * 64 + t * 16 + coL;
        bAddrBase[t] = (uint32_t)WOFF + co * 32 + (uint32_t)(bkh ^ (((coL >> 2) & 1) * 16));
    }
    int phA[2], pwA[2];
#pragma unroll
    for (int m = 0; m < 2; m++) {
        int p = warpM * 32 + m * 16 + arow;
        phA[m] = p >> 3;
        pwA[m] = p & 7;
    }

    // ---- precomputed halo producer descriptors (hoisted div/mod) ----
    const unsigned short* hsrc[4];
    uint32_t hdoff[4];
    int hsz[4];
#pragma unroll
    for (int v = 0; v < 4; v++) {
        int e = tid + 128 * v;
        bool ok = e < 400;
        int pix = e >> 2, split = (e >> 1) & 1, half = e & 1;
        int hh = pix / 10, ww = pix % 10;
        int hg = h0 - 1 + hh, wg = w0 - 1 + ww;
        bool inb = ok & (hg >= 0) & (hg < HIMG) & (wg >= 0) & (wg < WIMG);
        size_t off = inb ? ((size_t)n * 401408 + (hg * 56 + wg) * 16 + half * 8) : 0;
        hsrc[v]  = (split ? srcLo : srcHi) + off;
        hdoff[v] = split * 3200 + (uint32_t)((pix * 32 + half * 16) ^ ((ww & 4) << 2));
        hsz[v]   = ok ? (inb ? 16 : 0) : -1;
    }

    auto issue_chunk = [&](int ck, int buf) {
        const uint32_t bufo = sb + buf * BUFSZ;
        const size_t cko = (size_t)ck * 50176;   // 3136*16
#pragma unroll
        for (int v = 0; v < 4; v++)
            if (hsz[v] >= 0) cp16(bufo + hdoff[v], hsrc[v] + (hsz[v] ? cko : 0), hsz[v]);
        // weights: 2304 x 16B, linear in e2 (rs = e2>>8, u = e2&255)
        const unsigned short* wsrc = wInt + (size_t)ck * 18432;
#pragma unroll
        for (int j = 0; j < 18; j++) {
            int e2 = tid + 128 * j;
            cp16(bufo + WOFF + (uint32_t)((e2 * 16) ^ ((e2 & 8) << 1)), wsrc + e2 * 8, 16);
        }
        cp_commit();
    };

    float D[2][8][4];
#pragma unroll
    for (int m = 0; m < 2; m++)
#pragma unroll
        for (int f = 0; f < 8; f++)
#pragma unroll
            for (int j = 0; j < 4; j++) D[m][f][j] = 0.f;

    issue_chunk(0, 0);

    for (int ck = 0; ck < 8; ck++) {
        if (ck < 7) issue_chunk(ck + 1, (ck + 1) & 1);
        if (ck < 7) cp_wait<1>(); else cp_wait<0>();
        __syncthreads();

        const uint32_t sbuf = sb + (ck & 1) * BUFSZ;
#pragma unroll
        for (int rs = 0; rs < 9; rs++) {
            const int r = rs / 3, s = rs % 3;
            uint32_t ah[2][4], al[2][4];
#pragma unroll
            for (int m = 0; m < 2; m++) {
                const int wcol = pwA[m] + s;
                uint32_t aaddr = sbuf + (uint32_t)(((phA[m] + r) * 10 + wcol) * 32) +
                                 (uint32_t)(akh ^ (((wcol >> 2) & 1) * 16));
                ldsm4(ah[m], aaddr);
                ldsm4(al[m], aaddr + 3200);
            }
            const uint32_t bbase = sbuf + rs * 4096;
            uint32_t bi[4][4], bs[4][4];
#pragma unroll
            for (int t = 0; t < 4; t++) {
                ldsm4(bi[t], bbase + bAddrBase[t]);
#pragma unroll
                for (int q = 0; q < 4; q++) bs[t][q] = hscale11(bi[t][q]);
            }
#pragma unroll
            for (int m = 0; m < 2; m++)
#pragma unroll
                for (int t = 0; t < 4; t++)
#pragma unroll
                    for (int o = 0; o < 2; o++) {
                        const int nt = t * 2 + o;
                        mma16816(D[m][nt], ah[m], bi[t][o * 2], bi[t][o * 2 + 1]);
                        mma16816(D[m][nt], al[m], bs[t][o * 2], bs[t][o * 2 + 1]);
                    }
        }
        __syncthreads();
    }

    // ---------------- epilogue: BN+PACT into smem, coalesced writers ------
    float* qs = (float*)smem;           // [64 px][129] fp32 = 33KB
    const int qrow = lane >> 2;
    const int rr   = lane & 3;

#pragma unroll
    for (int m = 0; m < 2; m++)
#pragma unroll
        for (int nt = 0; nt < 8; nt++) {
            const int col = warpN * 64 + nt * 8;
#pragma unroll
            for (int j = 0; j < 4; j++) {
                const int co = col + 2 * rr + (j & 1);
                const int p  = warpM * 32 + m * 16 + qrow + (j >> 1) * 8;
                float d = D[m][nt][j] * wScl[co];
                float v, aa, ss, rr2;
                if (STAGE == 1) { v = d * g_bns1[co] + g_bnb1[co]; aa = g_a1p[co]; ss = g_s1[co]; rr2 = g_r1[co]; }
                else            { v = d * g_bns2[co] + g_bnb2[co]; aa = g_a2p[co]; ss = g_s2[co]; rr2 = g_r2[co]; }
                float cl2 = fminf(fmaxf(v, 0.f), aa);
                qs[p * 129 + co] = rintf(cl2 * rr2) * ss;
            }
        }
    __syncthreads();

    if (STAGE == 1) {
        const int split = tid >> 6;
        const int px    = tid & 63;
        const int h = h0 + (px >> 3), w = w0 + (px & 7);
#pragma unroll
        for (int g = 0; g < 8; g++) {
            unsigned short vals[16];
#pragma unroll
            for (int c = 0; c < 16; c++) {
                float q = qs[px * 129 + g * 16 + c];
                __half hh = __float2half_rn(q);
                if (split == 0) vals[c] = __half_as_ushort(hh);
                else vals[c] = __half_as_ushort(
                         __float2half_rn((q - __half2float(hh)) * 2048.0f));
            }
            size_t site = (((size_t)n * 8 + g) * 56 + h) * 56 + w;
            unsigned short* dst = (split ? g_a1lo : g_a1hi) + site * 16;
            ((uint4*)dst)[0] = ((uint4*)vals)[0];
            ((uint4*)dst)[1] = ((uint4*)vals)[1];
        }
    } else {
#pragma unroll
        for (int k = 0; k < 8; k++) {
            const int q   = tid + 128 * k;
            const int co  = q >> 3;
            const int hl  = q & 7;
            const int h   = h0 + hl;
            const float s3  = g_s3[co];
            const float r3  = g_r3[co];
            const float a3v = g_a3p[co];
            const size_t base = (((size_t)n * 128 + co) * 56 + h) * 56 + w0;
            float4 x0 = *(const float4*)(x_res + base);
            float4 x1 = *(const float4*)(x_res + base + 4);
            float xv[8] = {x0.x, x0.y, x0.z, x0.w, x1.x, x1.y, x1.z, x1.w};
            float ov[8];
#pragma unroll
            for (int w = 0; w < 8; w++) {
                float qv = qs[(hl * 8 + w) * 129 + co];
                float y  = rintf(qv * r3) * s3 + rintf(xv[w] * r3) * s3;
                float yc = fminf(fmaxf(y, 0.f), a3v);
                ov[w] = rintf(yc * r3) * s3;
            }
            *(float4*)(out + base)     = make_float4(ov[0], ov[1], ov[2], ov[3]);
            *(float4*)(out + base + 4) = make_float4(ov[4], ov[5], ov[6], ov[7]);
        }
    }
}

// ---------------- launch ----------------
extern "C" void kernel_launch(void* const* d_in, const int* in_sizes, int n_in,
                              void* d_out, int out_size) {
    const float* x  = (const float*)d_in[0];
    const float* w1 = (const float*)d_in[1];
    const float* g1 = (const float*)d_in[2];
    const float* b1 = (const float*)d_in[3];
    const float* m1 = (const float*)d_in[4];
    const float* v1 = (const float*)d_in[5];
    const float* a1 = (const float*)d_in[6];
    const float* w2 = (const float*)d_in[7];
    const float* g2 = (const float*)d_in[8];
    const float* b2 = (const float*)d_in[9];
    const float* m2 = (const float*)d_in[10];
    const float* v2 = (const float*)d_in[11];
    const float* a2 = (const float*)d_in[12];
    const float* a3 = (const float*)d_in[13];
    float* out = (float*)d_out;

    cudaFuncSetAttribute(conv_mma<1>, cudaFuncAttributeMaxDynamicSharedMemorySize, SMTOT);
    cudaFuncSetAttribute(conv_mma<2>, cudaFuncAttributeMaxDynamicSharedMemorySize, SMTOT);

    presplit_x<<<3136, 256>>>(x);
    prep_weights<<<dim3(128, 2), 256>>>(w1, w2);
    prep_params<<<1, 128>>>(g1, b1, m1, v1, a1, g2, b2, m2, v2, a2, a3);

    dim3 grid(7, 7, 32);
    conv_mma<1><<<grid, 128, SMTOT>>>(nullptr, nullptr);
    conv_mma<2><<<grid, 128, SMTOT>>>(x, out);
}

// round 10
// speedup vs baseline: 5.8282x; 1.0003x over previous
#include <cuda_runtime.h>
#include <cuda_fp16.h>
#include <math.h>
#include <stdint.h>

#define CCH   128
#define HIMG  56
#define WIMG  56
#define NIMG  32
#define EPSBN 1e-5f
#define QLEV  255.0f
#define WMAXQ 127.0f

#define NPIX ((size_t)NIMG * CCH * HIMG * WIMG)

// ---------------- device scratch ----------------
__device__ unsigned short g_xhi[NPIX],  g_xlo[NPIX];
__device__ unsigned short g_a1hi[NPIX], g_a1lo[NPIX];
#define WELEMS (8 * 9 * 128 * 16)
__device__ unsigned short g_w1i[WELEMS], g_w2i[WELEMS];
__device__ float g_ws1[CCH], g_ws2[CCH];
__device__ float g_bns1[CCH], g_bnb1[CCH], g_a1p[CCH], g_s1[CCH], g_r1[CCH];
__device__ float g_bns2[CCH], g_bnb2[CCH], g_a2p[CCH], g_s2[CCH], g_r2[CCH];
__device__ float g_a3p[CCH], g_s3[CCH], g_r3[CCH];

// ---------------- PTX helpers ----------------
__device__ __forceinline__ uint32_t smem_u32(const void* p) {
    uint32_t a;
    asm("{ .reg .u64 t; cvta.to.shared.u64 t, %1; cvt.u32.u64 %0, t; }" : "=r"(a) : "l"(p));
    return a;
}

__device__ __forceinline__ void cp16(uint32_t dst, const void* src, int sz) {
    asm volatile("cp.async.cg.shared.global [%0], [%1], 16, %2;"
                 :: "r"(dst), "l"(__cvta_generic_to_global(src)), "r"(sz) : "memory");
}
__device__ __forceinline__ void cp_commit() {
    asm volatile("cp.async.commit_group;" ::: "memory");
}
template <int N> __device__ __forceinline__ void cp_wait() {
    asm volatile("cp.async.wait_group %0;" :: "n"(N) : "memory");
}

__device__ __forceinline__ void ldsm4(uint32_t r[4], uint32_t addr) {
    asm volatile("ldmatrix.sync.aligned.m8n8.x4.shared.b16 {%0,%1,%2,%3}, [%4];"
                 : "=r"(r[0]), "=r"(r[1]), "=r"(r[2]), "=r"(r[3]) : "r"(addr));
}

__device__ __forceinline__ void mma16816(float d[4], const uint32_t a[4],
                                         uint32_t b0, uint32_t b1) {
    asm volatile("mma.sync.aligned.m16n8k16.row.col.f32.f16.f16.f32 "
                 "{%0,%1,%2,%3}, {%4,%5,%6,%7}, {%8,%9}, {%0,%1,%2,%3};"
                 : "+f"(d[0]), "+f"(d[1]), "+f"(d[2]), "+f"(d[3])
                 : "r"(a[0]), "r"(a[1]), "r"(a[2]), "r"(a[3]), "r"(b0), "r"(b1));
}

// exact exponent shift: x * 2^-11 on packed half2 (k integer => stays normal)
__device__ __forceinline__ uint32_t hscale11(uint32_t b) {
    const __half2 s = __floats2half2_rn(4.8828125e-4f, 4.8828125e-4f);
    __half2 v = *reinterpret_cast<__half2*>(&b);
    v = __hmul2(v, s);
    return *reinterpret_cast<uint32_t*>(&v);
}

// ---------------- prep kernels ----------------
__global__ void presplit_x(const float* __restrict__ x) {
    const size_t nsite = (size_t)NIMG * 8 * HIMG * WIMG;
    size_t i = (size_t)blockIdx.x * blockDim.x + threadIdx.x;
    if (i >= nsite) return;
    int w  = (int)(i % 56);
    int h  = (int)((i / 56) % 56);
    int ck = (int)((i / 3136) % 8);
    int n  = (int)(i / 25088);
    unsigned short hi[16], lo[16];
#pragma unroll
    for (int j = 0; j < 16; j++) {
        float v = x[((size_t)(n * 128 + ck * 16 + j)) * 3136 + h * 56 + w];
        __half hh = __float2half_rn(v);
        __half ll = __float2half_rn((v - __half2float(hh)) * 2048.0f);
        hi[j] = __half_as_ushort(hh);
        lo[j] = __half_as_ushort(ll);
    }
    uint4* dh = (uint4*)(g_xhi + i * 16);
    uint4* dl = (uint4*)(g_xlo + i * 16);
    dh[0] = ((uint4*)hi)[0]; dh[1] = ((uint4*)hi)[1];
    dl[0] = ((uint4*)lo)[0]; dl[1] = ((uint4*)lo)[1];
}

__global__ void prep_weights(const float* __restrict__ w1, const float* __restrict__ w2) {
    const int o = blockIdx.x;
    const float* w = (blockIdx.y == 0) ? w1 : w2;
    unsigned short* di = (blockIdx.y == 0) ? g_w1i : g_w2i;
    float* ws          = (blockIdx.y == 0) ? g_ws1 : g_ws2;
    const float* wo = w + (size_t)o * CCH * 9;

    float m = 0.f;
    for (int i = threadIdx.x; i < CCH * 9; i += blockDim.x)
        m = fmaxf(m, fabsf(wo[i]));
    __shared__ float red[256];
    red[threadIdx.x] = m;
    __syncthreads();
    for (int s = 128; s > 0; s >>= 1) {
        if (threadIdx.x < s) red[threadIdx.x] = fmaxf(red[threadIdx.x], red[threadIdx.x + s]);
        __syncthreads();
    }
    const float scale = fmaxf(red[0] / WMAXQ, 1e-8f);
    if (threadIdx.x == 0) ws[o] = scale;

    for (int i = threadIdx.x; i < CCH * 9; i += blockDim.x) {
        int ci = i / 9, rs = i % 9;
        float k = fminf(fmaxf(rintf(wo[i] / scale), -WMAXQ), WMAXQ);
        size_t d = ((size_t)(((ci >> 4) * 9 + rs) * 128 + o) << 4) + (ci & 15);
        di[d] = __half_as_ushort(__float2half_rn(k));
    }
}

__global__ void prep_params(const float* g1, const float* b1, const float* m1, const float* v1,
                            const float* a1, const float* g2, const float* b2, const float* m2,
                            const float* v2, const float* a2, const float* a3) {
    const int c = threadIdx.x;
    if (c >= CCH) return;
    float sc1 = g1[c] / sqrtf(v1[c] + EPSBN);
    g_bns1[c] = sc1; g_bnb1[c] = b1[c] - m1[c] * sc1; g_a1p[c] = a1[c];
    g_s1[c] = a1[c] / QLEV; g_r1[c] = 1.0f / g_s1[c];
    float sc2 = g2[c] / sqrtf(v2[c] + EPSBN);
    g_bns2[c] = sc2; g_bnb2[c] = b2[c] - m2[c] * sc2; g_a2p[c] = a2[c];
    g_s2[c] = a2[c] / QLEV; g_r2[c] = 1.0f / g_s2[c];
    g_a3p[c] = a3[c]; g_s3[c] = a3[c] / QLEV; g_r3[c] = 1.0f / g_s3[c];
}

// ---------------- smem layout per buffer ----------------
// [0,3200) halo hi ; [3200,6400) halo lo ; [6400,24832) weights [rs9][co64][ci16]
#define WOFF   6400
#define BUFSZ  24832
#define SMTOT  (2 * BUFSZ)

// ---------------- fused conv stage: CTA 64px x 64co, 2 warps of 32px x 64co
template <int STAGE>
__global__ void __launch_bounds__(64, 4)
conv_mma(const float* __restrict__ x_res, float* __restrict__ out) {
    extern __shared__ char smem[];
    const uint32_t sb = smem_u32(smem);

    const int tid   = threadIdx.x;
    const int lane  = tid & 31;
    const int warpM = tid >> 5;     // 2 warps over M (32 px each)

    const int w0  = (blockIdx.x >> 1) * 8;
    const int co0 = (blockIdx.x & 1) * 64;
    const int h0  = blockIdx.y * 8;
    const int n   = blockIdx.z;

    const unsigned short* __restrict__ srcHi = (STAGE == 1) ? g_xhi : g_a1hi;
    const unsigned short* __restrict__ srcLo = (STAGE == 1) ? g_xlo : g_a1lo;
    const unsigned short* __restrict__ wInt  = (STAGE == 1) ? g_w1i : g_w2i;
    const float* __restrict__ wScl           = (STAGE == 1) ? g_ws1 : g_ws2;

    // ---- ldmatrix lane addressing ----
    const int arow = lane & 15;
    const int akh  = (lane >> 4) * 16;
    const int bg   = lane >> 3;
    const int coL  = ((bg >> 1) << 3) + (lane & 7);
    const int bkh  = (bg & 1) * 16;
    uint32_t bAddrBase[4];
#pragma unroll
    for (int t = 0; t < 4; t++) {
        int co = t * 16 + coL;                 // local co 0..63
        bAddrBase[t] = (uint32_t)WOFF + co * 32 + (uint32_t)(bkh ^ (((coL >> 2) & 1) * 16));
    }
    int phA[2], pwA[2];
#pragma unroll
    for (int m = 0; m < 2; m++) {
        int p = warpM * 32 + m * 16 + arow;
        phA[m] = p >> 3;
        pwA[m] = p & 7;
    }

    // ---- precomputed halo producer descriptors (hoisted div/mod) ----
    const unsigned short* hsrc[7];
    uint32_t hdoff[7];
    int hsz[7];
#pragma unroll
    for (int v = 0; v < 7; v++) {
        int e = tid + 64 * v;
        bool ok = e < 400;
        int pix = e >> 2, split = (e >> 1) & 1, half = e & 1;
        int hh = pix / 10, ww = pix % 10;
        int hg = h0 - 1 + hh, wg = w0 - 1 + ww;
        bool inb = ok & (hg >= 0) & (hg < HIMG) & (wg >= 0) & (wg < WIMG);
        size_t off = inb ? ((size_t)n * 401408 + (hg * 56 + wg) * 16 + half * 8) : 0;
        hsrc[v]  = (split ? srcLo : srcHi) + off;
        hdoff[v] = split * 3200 + (uint32_t)((pix * 32 + half * 16) ^ ((ww & 4) << 2));
        hsz[v]   = ok ? (inb ? 16 : 0) : -1;
    }

    auto issue_chunk = [&](int ck, int buf) {
        const uint32_t bufo = sb + buf * BUFSZ;
        const size_t cko = (size_t)ck * 50176;   // 3136*16
#pragma unroll
        for (int v = 0; v < 7; v++)
            if (hsz[v] >= 0) cp16(bufo + hdoff[v], hsrc[v] + (hsz[v] ? cko : 0), hsz[v]);
        // weights: 1152 x 16B, rs = e2>>7, u = e2&127
        const unsigned short* wsrc = wInt + (size_t)ck * 18432 + co0 * 16;
#pragma unroll
        for (int j = 0; j < 18; j++) {
            int e2 = tid + 64 * j;
            int rs = e2 >> 7, u = e2 & 127;
            cp16(bufo + WOFF + (uint32_t)((e2 * 16) ^ ((e2 & 8) << 1)),
                 wsrc + rs * 2048 + u * 8, 16);
        }
        cp_commit();
    };

    float D[2][8][4];
#pragma unroll
    for (int m = 0; m < 2; m++)
#pragma unroll
        for (int f = 0; f < 8; f++)
#pragma unroll
            for (int j = 0; j < 4; j++) D[m][f][j] = 0.f;

    issue_chunk(0, 0);

    for (int ck = 0; ck < 8; ck++) {
        if (ck < 7) issue_chunk(ck + 1, (ck + 1) & 1);
        if (ck < 7) cp_wait<1>(); else cp_wait<0>();
        __syncthreads();

        const uint32_t sbuf = sb + (ck & 1) * BUFSZ;
#pragma unroll
        for (int rs = 0; rs < 9; rs++) {
            const int r = rs / 3, s = rs % 3;
            uint32_t ah[2][4], al[2][4];
#pragma unroll
            for (int m = 0; m < 2; m++) {
                const int wcol = pwA[m] + s;
                uint32_t aaddr = sbuf + (uint32_t)(((phA[m] + r) * 10 + wcol) * 32) +
                                 (uint32_t)(akh ^ (((wcol >> 2) & 1) * 16));
                ldsm4(ah[m], aaddr);
                ldsm4(al[m], aaddr + 3200);
            }
            const uint32_t bbase = sbuf + rs * 2048;
            uint32_t bi[4][4], bs[4][4];
#pragma unroll
            for (int t = 0; t < 4; t++) {
                ldsm4(bi[t], bbase + bAddrBase[t]);
#pragma unroll
                for (int q = 0; q < 4; q++) bs[t][q] = hscale11(bi[t][q]);
            }
#pragma unroll
            for (int m = 0; m < 2; m++)
#pragma unroll
                for (int t = 0; t < 4; t++)
#pragma unroll
                    for (int o = 0; o < 2; o++) {
                        const int nt = t * 2 + o;
                        mma16816(D[m][nt], ah[m], bi[t][o * 2], bi[t][o * 2 + 1]);
                        mma16816(D[m][nt], al[m], bs[t][o * 2], bs[t][o * 2 + 1]);
                    }
        }
        __syncthreads();
    }

    // ---------------- epilogue: BN+PACT into smem, coalesced writers ------
    float* qs = (float*)smem;           // [64 px][65] fp32 = 16.6KB
    const int qrow = lane >> 2;
    const int rr   = lane & 3;

#pragma unroll
    for (int m = 0; m < 2; m++)
#pragma unroll
        for (int nt = 0; nt < 8; nt++) {
            const int col = nt * 8;
#pragma unroll
            for (int j = 0; j < 4; j++) {
                const int cl_ = col + 2 * rr + (j & 1);   // local co 0..63
                const int co  = co0 + cl_;
                const int p   = warpM * 32 + m * 16 + qrow + (j >> 1) * 8;
                float d = D[m][nt][j] * wScl[co];
                float v, aa, ss, rr2;
                if (STAGE == 1) { v = d * g_bns1[co] + g_bnb1[co]; aa = g_a1p[co]; ss = g_s1[co]; rr2 = g_r1[co]; }
                else            { v = d * g_bns2[co] + g_bnb2[co]; aa = g_a2p[co]; ss = g_s2[co]; rr2 = g_r2[co]; }
                float cl2 = fminf(fmaxf(v, 0.f), aa);
                qs[p * 65 + cl_] = rintf(cl2 * rr2) * ss;
            }
        }
    __syncthreads();

    if (STAGE == 1) {
        const int px = tid;              // 64 px, one per thread
        const int h = h0 + (px >> 3), w = w0 + (px & 7);
#pragma unroll
        for (int g = 0; g < 4; g++) {
            unsigned short vh[16], vl[16];
#pragma unroll
            for (int c = 0; c < 16; c++) {
                float q = qs[px * 65 + g * 16 + c];
                __half hh = __float2half_rn(q);
                vh[c] = __half_as_ushort(hh);
                vl[c] = __half_as_ushort(__float2half_rn((q - __half2float(hh)) * 2048.0f));
            }
            const int ck = (co0 >> 4) + g;
            size_t site = (((size_t)n * 8 + ck) * 56 + h) * 56 + w;
            unsigned short* dh = g_a1hi + site * 16;
            unsigned short* dl = g_a1lo + site * 16;
            ((uint4*)dh)[0] = ((uint4*)vh)[0]; ((uint4*)dh)[1] = ((uint4*)vh)[1];
            ((uint4*)dl)[0] = ((uint4*)vl)[0]; ((uint4*)dl)[1] = ((uint4*)vl)[1];
        }
    } else {
#pragma unroll
        for (int k = 0; k < 8; k++) {
            const int q   = tid + 64 * k;   // 512 (co_l, h) rows
            const int cl_ = q >> 3;
            const int hl  = q & 7;
            const int co  = co0 + cl_;
            const int h   = h0 + hl;
            const float s3  = g_s3[co];
            const float r3  = g_r3[co];
            const float a3v = g_a3p[co];
            const size_t base = (((size_t)n * 128 + co) * 56 + h) * 56 + w0;
            float4 x0 = *(const float4*)(x_res + base);
            float4 x1 = *(const float4*)(x_res + base + 4);
            float xv[8] = {x0.x, x0.y, x0.z, x0.w, x1.x, x1.y, x1.z, x1.w};
            float ov[8];
#pragma unroll
            for (int w = 0; w < 8; w++) {
                float qv = qs[(hl * 8 + w) * 65 + cl_];
                float y  = rintf(qv * r3) * s3 + rintf(xv[w] * r3) * s3;
                float yc = fminf(fmaxf(y, 0.f), a3v);
                ov[w] = rintf(yc * r3) * s3;
            }
            *(float4*)(out + base)     = make_float4(ov[0], ov[1], ov[2], ov[3]);
            *(float4*)(out + base + 4) = make_float4(ov[4], ov[5], ov[6], ov[7]);
        }
    }
}

// ---------------- launch ----------------
extern "C" void kernel_launch(void* const* d_in, const int* in_sizes, int n_in,
                              void* d_out, int out_size) {
    const float* x  = (const float*)d_in[0];
    const float* w1 = (const float*)d_in[1];
    const float* g1 = (const float*)d_in[2];
    const float* b1 = (const float*)d_in[3];
    const float* m1 = (const float*)d_in[4];
    const float* v1 = (const float*)d_in[5];
    const float* a1 = (const float*)d_in[6];
    const float* w2 = (const float*)d_in[7];
    const float* g2 = (const float*)d_in[8];
    const float* b2 = (const float*)d_in[9];
    const float* m2 = (const float*)d_in[10];
    const float* v2 = (const float*)d_in[11];
    const float* a2 = (const float*)d_in[12];
    const float* a3 = (const float*)d_in[13];
    float* out = (float*)d_out;

    cudaFuncSetAttribute(conv_mma<1>, cudaFuncAttributeMaxDynamicSharedMemorySize, SMTOT);
    cudaFuncSetAttribute(conv_mma<2>, cudaFuncAttributeMaxDynamicSharedMemorySize, SMTOT);

    presplit_x<<<3136, 256>>>(x);
    prep_weights<<<dim3(128, 2), 256>>>(w1, w2);
    prep_params<<<1, 128>>>(g1, b1, m1, v1, a1, g2, b2, m2, v2, a2, a3);

    dim3 grid(14, 7, 32);   // x: 7 w-tiles x 2 co-groups
    conv_mma<1><<<grid, 64, SMTOT>>>(nullptr, nullptr);
    conv_mma<2><<<grid, 64, SMTOT>>>(x, out);
}